// round 2
// baseline (speedup 1.0000x reference)
#include <cuda_runtime.h>
#include <math.h>

// Problem constants
#define TT 256
#define BB 128
#define HH 512
#define H2 1024   // 2H
#define G4 2048   // 4H
#define NN 4096   // 2 dirs * 4H
#define CC 9

// ---------------- scratch (device globals; no runtime allocation) ----------------
__device__ float g_xs  [TT * BB * HH];   // embedded + renormed input, (t,b,h)
__device__ float g_pre [TT * BB * NN];   // input projection for current layer, ((t*B+b), dir*2048+g)
__device__ float g_hs0 [TT * BB * H2];   // layer-0 output (t,b,[hf|hb])
__device__ float g_hs1 [TT * BB * H2];   // layer-1 output
__device__ float g_c   [2 * BB * HH];    // cell state per dir (reused across layers)
__device__ float g_emis[TT * BB * CC];   // emissions (t,b,c)
__device__ float g_llh [BB];

// ---------------- 1) embedding gather + maxnorm renorm ----------------
__global__ void embed_kernel(const int* __restrict__ x, const float* __restrict__ embed) {
    int row = blockIdx.x;           // row = t*B + b
    int t = row / BB, b = row % BB;
    int tok = x[b * TT + t];
    const float* e = embed + (size_t)tok * HH;
    int tid = threadIdx.x;          // 128 threads, 4 elems each
    float v[4]; float ss = 0.f;
#pragma unroll
    for (int i = 0; i < 4; i++) { v[i] = e[tid + i * 128]; ss += v[i] * v[i]; }
    // reduce across 128 threads
    for (int o = 16; o; o >>= 1) ss += __shfl_xor_sync(0xffffffffu, ss, o);
    __shared__ float red[4];
    if ((tid & 31) == 0) red[tid >> 5] = ss;
    __syncthreads();
    float total = red[0] + red[1] + red[2] + red[3];
    float nrm = sqrtf(total);
    float sc = (nrm > 1.0f) ? 1.0f / (nrm + 1e-7f) : 1.0f;
    float* dst = g_xs + (size_t)row * HH;
#pragma unroll
    for (int i = 0; i < 4; i++) dst[tid + i * 128] = v[i] * sc;
}

// ---------------- 2) input projection GEMM: C = A @ W^T + bias -------------------
// A: (M=32768, K) row-major; W: (N=4096, K) row-major; out g_pre (M, 4096) row-major.
// Tiles: 128x128, BK=8, 256 threads, 8x8 register tile per thread.
template <int L>
__global__ void gemm_kernel(const float* __restrict__ W, const float* __restrict__ bias) {
    constexpr int K = (L == 0) ? HH : H2;
    const float* A = (L == 0) ? g_xs : g_hs0;
    float* Cout = g_pre;

    __shared__ float a_s[8][128];
    __shared__ float w_s[8][128];

    int m0 = blockIdx.y * 128;
    int n0 = blockIdx.x * 128;
    int tid = threadIdx.x;
    int ty = tid >> 4, tx = tid & 15;

    float acc[8][8];
#pragma unroll
    for (int i = 0; i < 8; i++)
#pragma unroll
        for (int j = 0; j < 8; j++) acc[i][j] = 0.f;

    int lr = tid >> 1;            // 0..127 (tile row)
    int lk = (tid & 1) * 4;       // 0 or 4
    const float* Arow = A + (size_t)(m0 + lr) * K + lk;
    const float* Wrow = W + (size_t)(n0 + lr) * K + lk;

    for (int k0 = 0; k0 < K; k0 += 8) {
        float4 av = *(const float4*)(Arow + k0);
        float4 wv = *(const float4*)(Wrow + k0);
        __syncthreads();
        a_s[lk + 0][lr] = av.x; a_s[lk + 1][lr] = av.y;
        a_s[lk + 2][lr] = av.z; a_s[lk + 3][lr] = av.w;
        w_s[lk + 0][lr] = wv.x; w_s[lk + 1][lr] = wv.y;
        w_s[lk + 2][lr] = wv.z; w_s[lk + 3][lr] = wv.w;
        __syncthreads();
#pragma unroll
        for (int kk = 0; kk < 8; kk++) {
            float af[8], wf[8];
            *(float4*)(af)     = *(const float4*)&a_s[kk][ty * 8];
            *(float4*)(af + 4) = *(const float4*)&a_s[kk][ty * 8 + 4];
            *(float4*)(wf)     = *(const float4*)&w_s[kk][tx * 8];
            *(float4*)(wf + 4) = *(const float4*)&w_s[kk][tx * 8 + 4];
#pragma unroll
            for (int i = 0; i < 8; i++)
#pragma unroll
                for (int j = 0; j < 8; j++) acc[i][j] += af[i] * wf[j];
        }
    }
#pragma unroll
    for (int i = 0; i < 8; i++) {
        size_t row = (size_t)(m0 + ty * 8 + i);
#pragma unroll
        for (int j = 0; j < 8; j++) {
            int col = n0 + tx * 8 + j;
            Cout[row * NN + col] = acc[i][j] + bias[col];
        }
    }
}

// ---------------- 3) recurrent step (both directions in one launch) --------------
// Block: 64 hidden units x 16 batches, one dir. grid = (8, 8, 2), 256 threads.
// z[b,g] = pre[tidx,b,dir,g] + sum_k h_prev[b,k] * w_hh[dir,g,k]; gates fused.
// h_prev is read from the hs buffer rows written by the previous step kernel.
template <int L>
__global__ void step_kernel(const float* __restrict__ w_hh, int s) {
    float* hs = (L == 0) ? g_hs0 : g_hs1;
    const float* hs_src = hs;

    int dir = blockIdx.z;
    int j0 = blockIdx.x * 64;
    int b0 = blockIdx.y * 16;
    int tid = threadIdx.x;
    int j = j0 + (tid & 63);
    int bg = tid >> 6;                   // 0..3 -> batches b0+bg*4 .. +3
    int tidx = (dir == 0) ? s : (TT - 1 - s);

    float acc[4][4];
#pragma unroll
    for (int g = 0; g < 4; g++)
#pragma unroll
        for (int x = 0; x < 4; x++) acc[g][x] = 0.f;

    if (s > 0) {
        int hprev_t = (dir == 0) ? (s - 1) : (TT - s);
        __shared__ float w_sm[16][256];
        __shared__ float h_sm[16][16];

        int lg = tid >> 6;               // loader gate 0..3
        int lj = tid & 63;               // loader hidden 0..63
        const float* wrow = w_hh + ((size_t)dir * G4 + (size_t)lg * HH + j0 + lj) * HH;
        int hk = tid >> 4, hb = tid & 15;
        const float* hrow = hs_src + ((size_t)hprev_t * BB + b0 + hb) * H2 + dir * HH;

        for (int k0 = 0; k0 < HH; k0 += 16) {
            float4 w0 = *(const float4*)(wrow + k0);
            float4 w1 = *(const float4*)(wrow + k0 + 4);
            float4 w2 = *(const float4*)(wrow + k0 + 8);
            float4 w3 = *(const float4*)(wrow + k0 + 12);
            float hv = hrow[k0 + hk];
            __syncthreads();
            int col = lg * 64 + lj;
            w_sm[0][col] = w0.x;  w_sm[1][col] = w0.y;  w_sm[2][col] = w0.z;  w_sm[3][col] = w0.w;
            w_sm[4][col] = w1.x;  w_sm[5][col] = w1.y;  w_sm[6][col] = w1.z;  w_sm[7][col] = w1.w;
            w_sm[8][col] = w2.x;  w_sm[9][col] = w2.y;  w_sm[10][col] = w2.z; w_sm[11][col] = w2.w;
            w_sm[12][col] = w3.x; w_sm[13][col] = w3.y; w_sm[14][col] = w3.z; w_sm[15][col] = w3.w;
            h_sm[hk][hb] = hv;
            __syncthreads();
#pragma unroll
            for (int kk = 0; kk < 16; kk++) {
                float4 h4 = *(const float4*)&h_sm[kk][bg * 4];
                float wv0 = w_sm[kk][(tid & 63)];
                float wv1 = w_sm[kk][64 + (tid & 63)];
                float wv2 = w_sm[kk][128 + (tid & 63)];
                float wv3 = w_sm[kk][192 + (tid & 63)];
                acc[0][0] += wv0 * h4.x; acc[0][1] += wv0 * h4.y; acc[0][2] += wv0 * h4.z; acc[0][3] += wv0 * h4.w;
                acc[1][0] += wv1 * h4.x; acc[1][1] += wv1 * h4.y; acc[1][2] += wv1 * h4.z; acc[1][3] += wv1 * h4.w;
                acc[2][0] += wv2 * h4.x; acc[2][1] += wv2 * h4.y; acc[2][2] += wv2 * h4.z; acc[2][3] += wv2 * h4.w;
                acc[3][0] += wv3 * h4.x; acc[3][1] += wv3 * h4.y; acc[3][2] += wv3 * h4.z; acc[3][3] += wv3 * h4.w;
            }
        }
    }

#pragma unroll
    for (int x = 0; x < 4; x++) {
        int b = b0 + bg * 4 + x;
        const float* p = g_pre + ((size_t)tidx * BB + b) * NN + (size_t)dir * G4;
        float zi = acc[0][x] + p[0 * HH + j];
        float zf = acc[1][x] + p[1 * HH + j];
        float zg = acc[2][x] + p[2 * HH + j];
        float zo = acc[3][x] + p[3 * HH + j];
        float* cptr = g_c + ((size_t)dir * BB + b) * HH + j;
        float cold = (s == 0) ? 0.f : *cptr;
        float ig = 1.f / (1.f + expf(-zi));
        float fg = 1.f / (1.f + expf(-zf));
        float og = 1.f / (1.f + expf(-zo));
        float cn = fg * cold + ig * tanhf(zg);
        float hn = og * tanhf(cn);
        *cptr = cn;
        hs[((size_t)tidx * BB + b) * H2 + (size_t)dir * HH + j] = hn;
    }
}

// ---------------- 4) emissions: (t,b,c) = hs1 . cls_w[c] + cls_b[c] --------------
__global__ void emis_kernel(const float* __restrict__ cls_w, const float* __restrict__ cls_b) {
    int warp = (blockIdx.x * blockDim.x + threadIdx.x) >> 5;   // row = t*B+b
    int lane = threadIdx.x & 31;
    const float* h = g_hs1 + (size_t)warp * H2;
    for (int c = 0; c < CC; c++) {
        const float* w = cls_w + c * H2;
        float sum = 0.f;
        for (int k = lane; k < H2; k += 32) sum += h[k] * w[k];
        for (int o = 16; o; o >>= 1) sum += __shfl_xor_sync(0xffffffffu, sum, o);
        if (lane == 0) g_emis[(size_t)warp * CC + c] = sum + cls_b[c];
    }
}

// ---------------- 5) CRF score + forward algorithm, one warp per batch -----------
__global__ void crf_kernel(const int* __restrict__ y,
                           const float* __restrict__ crf_start,
                           const float* __restrict__ crf_end,
                           const float* __restrict__ crf_trans) {
    int b = (blockIdx.x * blockDim.x + threadIdx.x) >> 5;
    int lane = threadIdx.x & 31;
    if (b >= BB) return;

    // ---- numerator score (lanes stride over t) ----
    float local = 0.f; int cnt = 0;
    for (int t = lane; t < TT; t += 32) {
        int yt = y[b * TT + t];
        int tag = yt > 0 ? yt : 0;
        float e = g_emis[((size_t)t * BB + b) * CC + tag];
        if (t == 0) {
            local += crf_start[tag] + e;
        } else {
            int yp = y[b * TT + t - 1];
            int tp = yp > 0 ? yp : 0;
            float m = (yt > -1) ? 1.f : 0.f;
            local += m * (crf_trans[tp * CC + tag] + e);
        }
        cnt += (yt > -1) ? 1 : 0;
    }
    for (int o = 16; o; o >>= 1) {
        local += __shfl_xor_sync(0xffffffffu, local, o);
        cnt   += __shfl_xor_sync(0xffffffffu, cnt, o);
    }
    int seq_end = cnt - 1;
    int ylast = y[b * TT + seq_end];
    float score = local + crf_end[ylast > 0 ? ylast : 0];

    // ---- denominator: forward algorithm, lanes 0..8 hold alpha[j] ----
    int j = lane < CC ? lane : (CC - 1);
    float tr[CC];
#pragma unroll
    for (int i = 0; i < CC; i++) tr[i] = crf_trans[i * CC + j];
    float alpha = crf_start[j] + g_emis[(size_t)b * CC + j];   // t = 0 row
    for (int t = 1; t < TT; t++) {
        float e = g_emis[((size_t)t * BB + b) * CC + j];
        float v[CC]; float m = -1e30f;
#pragma unroll
        for (int i = 0; i < CC; i++) {
            v[i] = __shfl_sync(0xffffffffu, alpha, i) + tr[i];
            m = fmaxf(m, v[i]);
        }
        float ssum = 0.f;
#pragma unroll
        for (int i = 0; i < CC; i++) ssum += expf(v[i] - m);
        float na = e + m + logf(ssum);
        bool mt = y[b * TT + t] > -1;
        alpha = mt ? na : alpha;
    }
    float val = (lane < CC) ? (alpha + crf_end[lane]) : -1e30f;
    float mm = val;
    for (int o = 16; o; o >>= 1) mm = fmaxf(mm, __shfl_xor_sync(0xffffffffu, mm, o));
    float se = expf(val - mm);
    for (int o = 16; o; o >>= 1) se += __shfl_xor_sync(0xffffffffu, se, o);
    float denom = mm + logf(se);
    if (lane == 0) g_llh[b] = score - denom;
}

// ---------------- 6) deterministic final reduction -------------------------------
__global__ void reduce_kernel(float* out) {
    __shared__ float sm[BB];
    int tid = threadIdx.x;
    sm[tid] = g_llh[tid];
    __syncthreads();
    for (int o = 64; o; o >>= 1) {
        if (tid < o) sm[tid] += sm[tid + o];
        __syncthreads();
    }
    if (tid == 0) out[0] = -sm[0] / (float)BB;
}

// ---------------- launch --------------------------------------------------------
extern "C" void kernel_launch(void* const* d_in, const int* in_sizes, int n_in,
                              void* d_out, int out_size) {
    (void)in_sizes; (void)n_in; (void)out_size;
    const int*   x         = (const int*)  d_in[0];
    const int*   y         = (const int*)  d_in[1];
    const float* embed     = (const float*)d_in[2];
    const float* w_ih_l0   = (const float*)d_in[3];
    const float* w_hh_l0   = (const float*)d_in[4];
    const float* b_l0      = (const float*)d_in[5];
    const float* w_ih_l1   = (const float*)d_in[6];
    const float* w_hh_l1   = (const float*)d_in[7];
    const float* b_l1      = (const float*)d_in[8];
    const float* cls_w     = (const float*)d_in[9];
    const float* cls_b     = (const float*)d_in[10];
    const float* crf_start = (const float*)d_in[11];
    const float* crf_end   = (const float*)d_in[12];
    const float* crf_trans = (const float*)d_in[13];
    float* out = (float*)d_out;

    embed_kernel<<<TT * BB, 128>>>(x, embed);

    gemm_kernel<0><<<dim3(NN / 128, (TT * BB) / 128), 256>>>(w_ih_l0, b_l0);
    for (int s = 0; s < TT; s++)
        step_kernel<0><<<dim3(8, 8, 2), 256>>>(w_hh_l0, s);

    gemm_kernel<1><<<dim3(NN / 128, (TT * BB) / 128), 256>>>(w_ih_l1, b_l1);
    for (int s = 0; s < TT; s++)
        step_kernel<1><<<dim3(8, 8, 2), 256>>>(w_hh_l1, s);

    emis_kernel<<<(TT * BB * 32) / 256, 256>>>(cls_w, cls_b);
    crf_kernel<<<16, 256>>>(y, crf_start, crf_end, crf_trans);
    reduce_kernel<<<1, 128>>>(out);
}

// round 3
// speedup vs baseline: 2.1184x; 2.1184x over previous
#include <cuda_runtime.h>
#include <math.h>

// Problem constants
#define TT 256
#define BB 128
#define HH 512
#define H2 1024   // 2H
#define G4 2048   // 4H
#define NN 4096   // 2 dirs * 4H
#define CC 9

// persistent-kernel tile constants
#define KC   64    // k-chunk staged per iteration
#define WPAD 36    // w_sm row stride (floats), 144B = 16B aligned
#define HPAD 132   // h_sm row stride
#define ZPAD 132   // z_sm row stride
#define NCTA 128   // persistent grid size (<= 148 SMs, 1 CTA/SM)

// ---------------- scratch (device globals; no runtime allocation) ----------------
__device__ float g_xs  [TT * BB * HH];   // embedded + renormed input, (t,b,h)
__device__ float g_pre [TT * BB * NN];   // input projection, ((t*B+b), dir*2048+g*512+j)
__device__ float g_hs0 [TT * BB * H2];   // layer-0 output (t,b,[hf|hb])
__device__ float g_hs1 [TT * BB * H2];   // layer-1 output
__device__ float g_c   [2 * BB * HH];    // cell state per dir (reused across layers)
__device__ float g_emis[TT * BB * CC];   // emissions (t,b,c)
__device__ float g_llh [BB];

// grid barrier state (monotonic phase; count always returns to 0)
__device__ unsigned g_bar_count = 0;
__device__ unsigned g_bar_phase = 0;

// ---------------- 1) embedding gather + maxnorm renorm ----------------
__global__ void embed_kernel(const int* __restrict__ x, const float* __restrict__ embed) {
    int row = blockIdx.x;           // row = t*B + b
    int t = row / BB, b = row % BB;
    int tok = x[b * TT + t];
    const float* e = embed + (size_t)tok * HH;
    int tid = threadIdx.x;          // 128 threads, 4 elems each
    float v[4]; float ss = 0.f;
#pragma unroll
    for (int i = 0; i < 4; i++) { v[i] = e[tid + i * 128]; ss += v[i] * v[i]; }
    for (int o = 16; o; o >>= 1) ss += __shfl_xor_sync(0xffffffffu, ss, o);
    __shared__ float red[4];
    if ((tid & 31) == 0) red[tid >> 5] = ss;
    __syncthreads();
    float total = red[0] + red[1] + red[2] + red[3];
    float nrm = sqrtf(total);
    float sc = (nrm > 1.0f) ? 1.0f / (nrm + 1e-7f) : 1.0f;
    float* dst = g_xs + (size_t)row * HH;
#pragma unroll
    for (int i = 0; i < 4; i++) dst[tid + i * 128] = v[i] * sc;
}

// ---------------- 2) input projection GEMM: C = A @ W^T + bias -------------------
template <int L>
__global__ void gemm_kernel(const float* __restrict__ W, const float* __restrict__ bias) {
    constexpr int K = (L == 0) ? HH : H2;
    const float* A = (L == 0) ? g_xs : g_hs0;
    float* Cout = g_pre;

    __shared__ float a_s[8][128];
    __shared__ float w_s[8][128];

    int m0 = blockIdx.y * 128;
    int n0 = blockIdx.x * 128;
    int tid = threadIdx.x;
    int ty = tid >> 4, tx = tid & 15;

    float acc[8][8];
#pragma unroll
    for (int i = 0; i < 8; i++)
#pragma unroll
        for (int j = 0; j < 8; j++) acc[i][j] = 0.f;

    int lr = tid >> 1;
    int lk = (tid & 1) * 4;
    const float* Arow = A + (size_t)(m0 + lr) * K + lk;
    const float* Wrow = W + (size_t)(n0 + lr) * K + lk;

    for (int k0 = 0; k0 < K; k0 += 8) {
        float4 av = *(const float4*)(Arow + k0);
        float4 wv = *(const float4*)(Wrow + k0);
        __syncthreads();
        a_s[lk + 0][lr] = av.x; a_s[lk + 1][lr] = av.y;
        a_s[lk + 2][lr] = av.z; a_s[lk + 3][lr] = av.w;
        w_s[lk + 0][lr] = wv.x; w_s[lk + 1][lr] = wv.y;
        w_s[lk + 2][lr] = wv.z; w_s[lk + 3][lr] = wv.w;
        __syncthreads();
#pragma unroll
        for (int kk = 0; kk < 8; kk++) {
            float af[8], wf[8];
            *(float4*)(af)     = *(const float4*)&a_s[kk][ty * 8];
            *(float4*)(af + 4) = *(const float4*)&a_s[kk][ty * 8 + 4];
            *(float4*)(wf)     = *(const float4*)&w_s[kk][tx * 8];
            *(float4*)(wf + 4) = *(const float4*)&w_s[kk][tx * 8 + 4];
#pragma unroll
            for (int i = 0; i < 8; i++)
#pragma unroll
                for (int j = 0; j < 8; j++) acc[i][j] += af[i] * wf[j];
        }
    }
#pragma unroll
    for (int i = 0; i < 8; i++) {
        size_t row = (size_t)(m0 + ty * 8 + i);
#pragma unroll
        for (int j = 0; j < 8; j++) {
            int col = n0 + tx * 8 + j;
            Cout[row * NN + col] = acc[i][j] + bias[col];
        }
    }
}

// ---------------- 3) persistent recurrent kernel (all 256 steps, both dirs) ------
// 128 CTAs, 256 threads. CTA ct: dir = ct>>6, owns 8 hidden j (j0 = (ct&63)*8)
// i.e. 32 weight rows (4 gates x 8 j) kept resident in SMEM for the whole kernel.
// Per step: z[32r x 128b] = W_sm @ h_prev  (register-tiled), then fused gates.
// Grid barrier between steps (all CTAs co-resident: 128 <= 148 SMs, 1 CTA/SM).
template <int L>
__global__ void __launch_bounds__(256, 1) recurrent_kernel(const float* __restrict__ w_hh) {
    extern __shared__ float sm[];
    float* w_sm = sm;                       // [512][WPAD]
    float* h_sm = w_sm + 512 * WPAD;        // [KC][HPAD]
    float* z_sm = h_sm + KC * HPAD;         // [32][ZPAD]

    float* hs = (L == 0) ? g_hs0 : g_hs1;
    const int tid = threadIdx.x;
    const int ct  = blockIdx.x;
    const int dir = ct >> 6;
    const int j0  = (ct & 63) * 8;

    // snapshot barrier phase (stable: no CTA can bump phase until all have started)
    unsigned phase0 = *(volatile unsigned*)&g_bar_phase;

    // --- load resident weights: local row r = g*8+jj  <->  w_hh[dir][g*512+j0+jj][:] ---
    for (int i = 0; i < 16; i++) {
        int lin = tid + i * 256;            // over 32 rows x 128 float4
        int r   = lin & 31;
        int kq  = lin >> 5;
        int g   = r >> 3, jj = r & 7;
        float4 wv = *(const float4*)(w_hh + ((size_t)(dir * G4 + g * HH + j0 + jj)) * HH + kq * 4);
        w_sm[(kq * 4 + 0) * WPAD + r] = wv.x;
        w_sm[(kq * 4 + 1) * WPAD + r] = wv.y;
        w_sm[(kq * 4 + 2) * WPAD + r] = wv.z;
        w_sm[(kq * 4 + 3) * WPAD + r] = wv.w;
    }
    __syncthreads();

    const int r4 = tid >> 5;   // 0..7  -> local rows r4*4 .. r4*4+3
    const int b4 = tid & 31;   // 0..31 -> batches   b4*4 .. b4*4+3

    for (int s = 0; s < TT; s++) {
        const int tidx = dir ? (TT - 1 - s) : s;

        float acc[4][4];
#pragma unroll
        for (int i = 0; i < 4; i++)
#pragma unroll
            for (int j = 0; j < 4; j++) acc[i][j] = 0.f;

        if (s > 0) {
            const int hp = dir ? (TT - s) : (s - 1);
            const float* hbase = hs + ((size_t)hp * BB) * H2 + (size_t)dir * HH;
            for (int k0 = 0; k0 < HH; k0 += KC) {
                __syncthreads();
                // stage h chunk: 128 b x KC k  (coalesced float4 reads)
#pragma unroll
                for (int i = 0; i < (BB * KC / 4) / 256; i++) {   // 8 iters
                    int lin = tid + i * 256;
                    int b   = lin >> 4;       // 16 float4 per batch
                    int kq  = lin & 15;
                    float4 hv = *(const float4*)(hbase + (size_t)b * H2 + k0 + kq * 4);
                    h_sm[(kq * 4 + 0) * HPAD + b] = hv.x;
                    h_sm[(kq * 4 + 1) * HPAD + b] = hv.y;
                    h_sm[(kq * 4 + 2) * HPAD + b] = hv.z;
                    h_sm[(kq * 4 + 3) * HPAD + b] = hv.w;
                }
                __syncthreads();
#pragma unroll 8
                for (int kk = 0; kk < KC; kk++) {
                    float4 wv = *(const float4*)&w_sm[(k0 + kk) * WPAD + r4 * 4];
                    float4 hv = *(const float4*)&h_sm[kk * HPAD + b4 * 4];
                    acc[0][0] += wv.x * hv.x; acc[0][1] += wv.x * hv.y; acc[0][2] += wv.x * hv.z; acc[0][3] += wv.x * hv.w;
                    acc[1][0] += wv.y * hv.x; acc[1][1] += wv.y * hv.y; acc[1][2] += wv.y * hv.z; acc[1][3] += wv.y * hv.w;
                    acc[2][0] += wv.z * hv.x; acc[2][1] += wv.z * hv.y; acc[2][2] += wv.z * hv.z; acc[2][3] += wv.z * hv.w;
                    acc[3][0] += wv.w * hv.x; acc[3][1] += wv.w * hv.y; acc[3][2] += wv.w * hv.z; acc[3][3] += wv.w * hv.w;
                }
            }
        }

        // --- exchange z partials so each thread owns all 4 gates of its (j,b) ---
        __syncthreads();
#pragma unroll
        for (int rr = 0; rr < 4; rr++)
            *(float4*)&z_sm[(r4 * 4 + rr) * ZPAD + b4 * 4] =
                make_float4(acc[rr][0], acc[rr][1], acc[rr][2], acc[rr][3]);
        __syncthreads();

        // --- fused LSTM pointwise: thread -> (b = tid>>1, 4 j's) ---
        {
            const int b  = tid >> 1;
            const int jh = (tid & 1) * 4;
            const float* p = g_pre + ((size_t)tidx * BB + b) * NN + (size_t)dir * G4;
            float4 p0 = *(const float4*)(p + 0 * HH + j0 + jh);
            float4 p1 = *(const float4*)(p + 1 * HH + j0 + jh);
            float4 p2 = *(const float4*)(p + 2 * HH + j0 + jh);
            float4 p3 = *(const float4*)(p + 3 * HH + j0 + jh);
            float* cptr = g_c + ((size_t)dir * BB + b) * HH + j0 + jh;
            float4 cold = (s == 0) ? make_float4(0.f, 0.f, 0.f, 0.f) : *(float4*)cptr;
            float hn[4], cn[4];
            float pi[4] = {p0.x, p0.y, p0.z, p0.w};
            float pf[4] = {p1.x, p1.y, p1.z, p1.w};
            float pg[4] = {p2.x, p2.y, p2.z, p2.w};
            float po[4] = {p3.x, p3.y, p3.z, p3.w};
            float co[4] = {cold.x, cold.y, cold.z, cold.w};
#pragma unroll
            for (int x = 0; x < 4; x++) {
                int jj = jh + x;
                float zi = z_sm[(0 * 8 + jj) * ZPAD + b] + pi[x];
                float zf = z_sm[(1 * 8 + jj) * ZPAD + b] + pf[x];
                float zg = z_sm[(2 * 8 + jj) * ZPAD + b] + pg[x];
                float zo = z_sm[(3 * 8 + jj) * ZPAD + b] + po[x];
                float ig = 1.f / (1.f + expf(-zi));
                float fg = 1.f / (1.f + expf(-zf));
                float og = 1.f / (1.f + expf(-zo));
                cn[x] = fg * co[x] + ig * tanhf(zg);
                hn[x] = og * tanhf(cn[x]);
            }
            *(float4*)cptr = make_float4(cn[0], cn[1], cn[2], cn[3]);
            *(float4*)(hs + ((size_t)tidx * BB + b) * H2 + (size_t)dir * HH + j0 + jh) =
                make_float4(hn[0], hn[1], hn[2], hn[3]);
        }

        // --- grid barrier (not needed after the last step) ---
        if (s < TT - 1) {
            __threadfence();
            __syncthreads();
            if (tid == 0) {
                unsigned ticket = atomicAdd(&g_bar_count, 1u);
                if (ticket == NCTA - 1) {
                    g_bar_count = 0;
                    __threadfence();
                    atomicAdd(&g_bar_phase, 1u);
                } else {
                    unsigned target = phase0 + (unsigned)(s + 1);
                    while ((int)(*(volatile unsigned*)&g_bar_phase - target) < 0)
                        __nanosleep(32);
                }
                __threadfence();
            }
            __syncthreads();
        }
    }
}

// ---------------- 4) emissions: (t,b,c) = hs1 . cls_w[c] + cls_b[c] --------------
__global__ void emis_kernel(const float* __restrict__ cls_w, const float* __restrict__ cls_b) {
    int warp = (blockIdx.x * blockDim.x + threadIdx.x) >> 5;
    int lane = threadIdx.x & 31;
    const float* h = g_hs1 + (size_t)warp * H2;
    for (int c = 0; c < CC; c++) {
        const float* w = cls_w + c * H2;
        float sum = 0.f;
        for (int k = lane; k < H2; k += 32) sum += h[k] * w[k];
        for (int o = 16; o; o >>= 1) sum += __shfl_xor_sync(0xffffffffu, sum, o);
        if (lane == 0) g_emis[(size_t)warp * CC + c] = sum + cls_b[c];
    }
}

// ---------------- 5) CRF score + forward algorithm, one warp per batch -----------
__global__ void crf_kernel(const int* __restrict__ y,
                           const float* __restrict__ crf_start,
                           const float* __restrict__ crf_end,
                           const float* __restrict__ crf_trans) {
    int b = (blockIdx.x * blockDim.x + threadIdx.x) >> 5;
    int lane = threadIdx.x & 31;
    if (b >= BB) return;

    float local = 0.f; int cnt = 0;
    for (int t = lane; t < TT; t += 32) {
        int yt = y[b * TT + t];
        int tag = yt > 0 ? yt : 0;
        float e = g_emis[((size_t)t * BB + b) * CC + tag];
        if (t == 0) {
            local += crf_start[tag] + e;
        } else {
            int yp = y[b * TT + t - 1];
            int tp = yp > 0 ? yp : 0;
            float m = (yt > -1) ? 1.f : 0.f;
            local += m * (crf_trans[tp * CC + tag] + e);
        }
        cnt += (yt > -1) ? 1 : 0;
    }
    for (int o = 16; o; o >>= 1) {
        local += __shfl_xor_sync(0xffffffffu, local, o);
        cnt   += __shfl_xor_sync(0xffffffffu, cnt, o);
    }
    int seq_end = cnt - 1;
    int ylast = y[b * TT + seq_end];
    float score = local + crf_end[ylast > 0 ? ylast : 0];

    int j = lane < CC ? lane : (CC - 1);
    float tr[CC];
#pragma unroll
    for (int i = 0; i < CC; i++) tr[i] = crf_trans[i * CC + j];
    float alpha = crf_start[j] + g_emis[(size_t)b * CC + j];
    for (int t = 1; t < TT; t++) {
        float e = g_emis[((size_t)t * BB + b) * CC + j];
        float v[CC]; float m = -1e30f;
#pragma unroll
        for (int i = 0; i < CC; i++) {
            v[i] = __shfl_sync(0xffffffffu, alpha, i) + tr[i];
            m = fmaxf(m, v[i]);
        }
        float ssum = 0.f;
#pragma unroll
        for (int i = 0; i < CC; i++) ssum += expf(v[i] - m);
        float na = e + m + logf(ssum);
        bool mt = y[b * TT + t] > -1;
        alpha = mt ? na : alpha;
    }
    float val = (lane < CC) ? (alpha + crf_end[lane]) : -1e30f;
    float mm = val;
    for (int o = 16; o; o >>= 1) mm = fmaxf(mm, __shfl_xor_sync(0xffffffffu, mm, o));
    float se = expf(val - mm);
    for (int o = 16; o; o >>= 1) se += __shfl_xor_sync(0xffffffffu, se, o);
    float denom = mm + logf(se);
    if (lane == 0) g_llh[b] = score - denom;
}

// ---------------- 6) deterministic final reduction -------------------------------
__global__ void reduce_kernel(float* out) {
    __shared__ float sm[BB];
    int tid = threadIdx.x;
    sm[tid] = g_llh[tid];
    __syncthreads();
    for (int o = 64; o; o >>= 1) {
        if (tid < o) sm[tid] += sm[tid + o];
        __syncthreads();
    }
    if (tid == 0) out[0] = -sm[0] / (float)BB;
}

// ---------------- launch --------------------------------------------------------
extern "C" void kernel_launch(void* const* d_in, const int* in_sizes, int n_in,
                              void* d_out, int out_size) {
    (void)in_sizes; (void)n_in; (void)out_size;
    const int*   x         = (const int*)  d_in[0];
    const int*   y         = (const int*)  d_in[1];
    const float* embed     = (const float*)d_in[2];
    const float* w_ih_l0   = (const float*)d_in[3];
    const float* w_hh_l0   = (const float*)d_in[4];
    const float* b_l0      = (const float*)d_in[5];
    const float* w_ih_l1   = (const float*)d_in[6];
    const float* w_hh_l1   = (const float*)d_in[7];
    const float* b_l1      = (const float*)d_in[8];
    const float* cls_w     = (const float*)d_in[9];
    const float* cls_b     = (const float*)d_in[10];
    const float* crf_start = (const float*)d_in[11];
    const float* crf_end   = (const float*)d_in[12];
    const float* crf_trans = (const float*)d_in[13];
    float* out = (float*)d_out;

    const int SMEM_BYTES = (512 * WPAD + KC * HPAD + 32 * ZPAD) * 4;  // 124416
    static bool attr_set = false;
    if (!attr_set) {
        cudaFuncSetAttribute(recurrent_kernel<0>, cudaFuncAttributeMaxDynamicSharedMemorySize, SMEM_BYTES);
        cudaFuncSetAttribute(recurrent_kernel<1>, cudaFuncAttributeMaxDynamicSharedMemorySize, SMEM_BYTES);
        attr_set = true;
    }

    embed_kernel<<<TT * BB, 128>>>(x, embed);

    gemm_kernel<0><<<dim3(NN / 128, (TT * BB) / 128), 256>>>(w_ih_l0, b_l0);
    recurrent_kernel<0><<<NCTA, 256, SMEM_BYTES>>>(w_hh_l0);

    gemm_kernel<1><<<dim3(NN / 128, (TT * BB) / 128), 256>>>(w_ih_l1, b_l1);
    recurrent_kernel<1><<<NCTA, 256, SMEM_BYTES>>>(w_hh_l1);

    emis_kernel<<<(TT * BB * 32) / 256, 256>>>(cls_w, cls_b);
    crf_kernel<<<16, 256>>>(y, crf_start, crf_end, crf_trans);
    reduce_kernel<<<1, 128>>>(out);
}

// round 4
// speedup vs baseline: 5.1864x; 2.4483x over previous
#include <cuda_runtime.h>
#include <math.h>

// Problem constants
#define TT 256
#define BB 128
#define HH 512
#define H2 1024   // 2H
#define G4 2048   // 4H
#define NN 4096   // 2 dirs * 4H
#define CC 9
#define NCTA 128
#define ZPAD 132

// ---------------- scratch (device globals) ----------------
__device__ float    g_xs  [TT * BB * HH];
__device__ float    g_pre [TT * BB * NN];
__device__ float    g_hs0 [TT * BB * H2];
__device__ float    g_hs1 [TT * BB * H2];
__device__ float    g_c   [2 * BB * HH];
__device__ unsigned g_htf [2 * BB * HH];   // tf32 bits of h_prev per dir (ping buffer)
__device__ float    g_emis[TT * BB * CC];
__device__ float    g_llh [BB];
__device__ unsigned g_bar_count = 0;
__device__ unsigned g_bar_phase = 0;

// ---------------- tf32 helpers ----------------
__device__ __forceinline__ unsigned f2tf(float x) {
    unsigned u; asm("cvt.rna.tf32.f32 %0, %1;" : "=r"(u) : "f"(x)); return u;
}
__device__ __forceinline__ void mma_tf32(float* c, unsigned a0, unsigned a1,
                                         unsigned a2, unsigned a3,
                                         unsigned b0, unsigned b1) {
    asm volatile("mma.sync.aligned.m16n8k8.row.col.f32.tf32.tf32.f32 "
                 "{%0,%1,%2,%3}, {%4,%5,%6,%7}, {%8,%9}, {%0,%1,%2,%3};"
                 : "+f"(c[0]), "+f"(c[1]), "+f"(c[2]), "+f"(c[3])
                 : "r"(a0), "r"(a1), "r"(a2), "r"(a3), "r"(b0), "r"(b1));
}

// ---------------- 1) embedding gather + maxnorm renorm ----------------
__global__ void embed_kernel(const int* __restrict__ x, const float* __restrict__ embed) {
    int row = blockIdx.x;           // row = t*B + b
    int t = row / BB, b = row % BB;
    int tok = x[b * TT + t];
    const float* e = embed + (size_t)tok * HH;
    int tid = threadIdx.x;
    float v[4]; float ss = 0.f;
#pragma unroll
    for (int i = 0; i < 4; i++) { v[i] = e[tid + i * 128]; ss += v[i] * v[i]; }
    for (int o = 16; o; o >>= 1) ss += __shfl_xor_sync(0xffffffffu, ss, o);
    __shared__ float red[4];
    if ((tid & 31) == 0) red[tid >> 5] = ss;
    __syncthreads();
    float total = red[0] + red[1] + red[2] + red[3];
    float nrm = sqrtf(total);
    float sc = (nrm > 1.0f) ? 1.0f / (nrm + 1e-7f) : 1.0f;
    float* dst = g_xs + (size_t)row * HH;
#pragma unroll
    for (int i = 0; i < 4; i++) dst[tid + i * 128] = v[i] * sc;
}

// ---------------- 2) input projection GEMM (tf32 tensor cores) -------------------
// C(32768 x 4096) = A(M,K) @ W(4096,K)^T + bias. CTA tile 128x128, BK=16,
// 8 warps (2m x 4n), warp tile 64x32 via m16n8k8 tf32 mma.
template <int L>
__global__ void __launch_bounds__(256) gemm_kernel(const float* __restrict__ W,
                                                   const float* __restrict__ bias) {
    constexpr int K = (L == 0) ? HH : H2;
    const float* A = (L == 0) ? g_xs : g_hs0;

    __shared__ unsigned a_s[16 * 136];   // [k][m], stride 136 (==8 mod 32: conflict-free frags)
    __shared__ unsigned b_s[16 * 136];   // [k][n]

    const int m0 = blockIdx.y * 128, n0 = blockIdx.x * 128;
    const int tid = threadIdx.x;
    const int w = tid >> 5, lane = tid & 31;
    const int wm = w >> 2, wn = w & 3;
    const int lr = lane >> 2, lc = lane & 3;

    float acc[4][4][4];
#pragma unroll
    for (int i = 0; i < 4; i++)
#pragma unroll
        for (int j = 0; j < 4; j++)
#pragma unroll
            for (int q = 0; q < 4; q++) acc[i][j][q] = 0.f;

    for (int k0 = 0; k0 < K; k0 += 16) {
        __syncthreads();
#pragma unroll
        for (int i = 0; i < 2; i++) {
            int lin = tid + i * 256;            // 0..511
            int row = lin >> 2, q = lin & 3;
            float4 av = *(const float4*)(A + (size_t)(m0 + row) * K + k0 + q * 4);
            a_s[(q * 4 + 0) * 136 + row] = f2tf(av.x);
            a_s[(q * 4 + 1) * 136 + row] = f2tf(av.y);
            a_s[(q * 4 + 2) * 136 + row] = f2tf(av.z);
            a_s[(q * 4 + 3) * 136 + row] = f2tf(av.w);
            float4 wv = *(const float4*)(W + (size_t)(n0 + row) * K + k0 + q * 4);
            b_s[(q * 4 + 0) * 136 + row] = f2tf(wv.x);
            b_s[(q * 4 + 1) * 136 + row] = f2tf(wv.y);
            b_s[(q * 4 + 2) * 136 + row] = f2tf(wv.z);
            b_s[(q * 4 + 3) * 136 + row] = f2tf(wv.w);
        }
        __syncthreads();
#pragma unroll
        for (int kk = 0; kk < 16; kk += 8) {
            unsigned af[4][4], bf[4][2];
#pragma unroll
            for (int mf = 0; mf < 4; mf++) {
                int r = wm * 64 + mf * 16 + lr;
                af[mf][0] = a_s[(kk + lc) * 136 + r];
                af[mf][1] = a_s[(kk + lc) * 136 + r + 8];
                af[mf][2] = a_s[(kk + lc + 4) * 136 + r];
                af[mf][3] = a_s[(kk + lc + 4) * 136 + r + 8];
            }
#pragma unroll
            for (int nf = 0; nf < 4; nf++) {
                int n = wn * 32 + nf * 8 + lr;
                bf[nf][0] = b_s[(kk + lc) * 136 + n];
                bf[nf][1] = b_s[(kk + lc + 4) * 136 + n];
            }
#pragma unroll
            for (int mf = 0; mf < 4; mf++)
#pragma unroll
                for (int nf = 0; nf < 4; nf++)
                    mma_tf32(acc[mf][nf], af[mf][0], af[mf][1], af[mf][2], af[mf][3],
                             bf[nf][0], bf[nf][1]);
        }
    }
    // epilogue
#pragma unroll
    for (int nf = 0; nf < 4; nf++) {
        int col = n0 + wn * 32 + nf * 8 + 2 * lc;
        float b0v = bias[col], b1v = bias[col + 1];
#pragma unroll
        for (int mf = 0; mf < 4; mf++) {
            int row = m0 + wm * 64 + mf * 16 + lr;
            *(float2*)&g_pre[(size_t)row * NN + col] =
                make_float2(acc[mf][nf][0] + b0v, acc[mf][nf][1] + b1v);
            *(float2*)&g_pre[(size_t)(row + 8) * NN + col] =
                make_float2(acc[mf][nf][2] + b0v, acc[mf][nf][3] + b1v);
        }
    }
}

// ---------------- 3) persistent recurrent kernel (tf32 mma) ----------------------
// 128 CTAs. CTA ct: dir = ct>>6, j0 = (ct&63)*8 -> 32 z-rows (4 gates x 8 j).
// W_hh (32x512) resident in SMEM pre-packed into mma A-fragment float4s.
// h_prev published as tf32 bits in g_htf by the previous step's pointwise stage.
// z = W @ h^T via m16n8k8; warps: wh = w>>2 (row half), wn = w&3 (32 batches).
template <int L>
__global__ void __launch_bounds__(256, 1) recurrent_kernel(const float* __restrict__ w_hh) {
    extern __shared__ unsigned smu[];
    uint4* wpack = (uint4*)smu;             // [ks(64)][c(4)][half(2)] x (9 float4: 8 rows + pad)
    uint4* hpack = wpack + 64 * 4 * 2 * 9;  // [q'(32)] x (129 uint4: 128 b + pad)
    float* z_sm  = (float*)(hpack + 32 * 129);  // [32][ZPAD]

    float* hs = (L == 0) ? g_hs0 : g_hs1;
    const int tid = threadIdx.x;
    const int ct  = blockIdx.x;
    const int dir = ct >> 6;
    const int j0  = (ct & 63) * 8;
    const int w = tid >> 5, lane = tid & 31;
    const int wh = w >> 2, wn = w & 3;
    const int lr = lane >> 2, lc = lane & 3;

    unsigned phase0 = *(volatile unsigned*)&g_bar_phase;

    // --- pack resident weights into A-fragment layout (tf32) ---
#pragma unroll
    for (int i = 0; i < 16; i++) {
        int lin = tid + i * 256;             // 0..4095 over 32 rows x 128 float4
        int r  = lin >> 7;                   // local row = g*8+jj
        int k4 = lin & 127;
        const float* wr = w_hh + ((size_t)dir * G4 + (size_t)(r >> 3) * HH + j0 + (r & 7)) * HH + k4 * 4;
        float4 wv = *(const float4*)wr;
        unsigned vals[4] = {f2tf(wv.x), f2tf(wv.y), f2tf(wv.z), f2tf(wv.w)};
        int half = r >> 4, row = r & 7, ybit = (r >> 3) & 1;
#pragma unroll
        for (int j = 0; j < 4; j++) {
            int k = k4 * 4 + j;
            int ks = k >> 3, c = k & 3, kh = (k >> 2) & 1;
            ((unsigned*)&wpack[((ks * 4 + c) * 2 + half) * 9 + row])[ybit + 2 * kh] = vals[j];
        }
    }
    __syncthreads();

    for (int s = 0; s < TT; s++) {
        const int tidx = dir ? (TT - 1 - s) : s;

        float acc[4][4];
#pragma unroll
        for (int nf = 0; nf < 4; nf++)
#pragma unroll
            for (int q = 0; q < 4; q++) acc[nf][q] = 0.f;

        if (s > 0) {
            const unsigned* hsrc = g_htf + (size_t)dir * BB * HH;
            for (int kc = 0; kc < 4; kc++) {          // 4 chunks of 128 k
                __syncthreads();
#pragma unroll
                for (int i = 0; i < 16; i++) {        // stage chunk: tf32 bits, packed
                    int lin = tid + i * 256;          // 0..4095
                    int b = lin >> 5, q = lin & 31;
                    uint4 hv = *(const uint4*)(hsrc + (size_t)b * HH + kc * 128 + q * 4);
                    hpack[q * 129 + b] = hv;          // q = ls*2 + khalf
                }
                __syncthreads();
#pragma unroll
                for (int ls = 0; ls < 16; ls++) {
                    int ks = kc * 16 + ls;
                    uint4 aa = wpack[((ks * 4 + lc) * 2 + wh) * 9 + lr];
#pragma unroll
                    for (int nf = 0; nf < 4; nf++) {
                        int b = wn * 32 + nf * 8 + lr;
                        unsigned b0 = ((const unsigned*)&hpack[(ls * 2 + 0) * 129 + b])[lc];
                        unsigned b1 = ((const unsigned*)&hpack[(ls * 2 + 1) * 129 + b])[lc];
                        mma_tf32(acc[nf], aa.x, aa.y, aa.z, aa.w, b0, b1);
                    }
                }
            }
        }

        // --- z exchange ---
        __syncthreads();
#pragma unroll
        for (int nf = 0; nf < 4; nf++) {
            int row = wh * 16 + lr;
            int col = wn * 32 + nf * 8 + 2 * lc;
            *(float2*)&z_sm[row * ZPAD + col]       = make_float2(acc[nf][0], acc[nf][1]);
            *(float2*)&z_sm[(row + 8) * ZPAD + col] = make_float2(acc[nf][2], acc[nf][3]);
        }
        __syncthreads();

        // --- fused LSTM pointwise: thread -> (b = tid>>1, 4 j's) ---
        {
            const int b  = tid >> 1;
            const int jh = (tid & 1) * 4;
            const float* p = g_pre + ((size_t)tidx * BB + b) * NN + (size_t)dir * G4;
            float4 p0 = *(const float4*)(p + 0 * HH + j0 + jh);
            float4 p1 = *(const float4*)(p + 1 * HH + j0 + jh);
            float4 p2 = *(const float4*)(p + 2 * HH + j0 + jh);
            float4 p3 = *(const float4*)(p + 3 * HH + j0 + jh);
            float* cptr = g_c + ((size_t)dir * BB + b) * HH + j0 + jh;
            float4 cold = (s == 0) ? make_float4(0.f, 0.f, 0.f, 0.f) : *(float4*)cptr;
            float pi[4] = {p0.x, p0.y, p0.z, p0.w};
            float pf[4] = {p1.x, p1.y, p1.z, p1.w};
            float pg[4] = {p2.x, p2.y, p2.z, p2.w};
            float po[4] = {p3.x, p3.y, p3.z, p3.w};
            float co[4] = {cold.x, cold.y, cold.z, cold.w};
            float hn[4], cn[4];
#pragma unroll
            for (int x = 0; x < 4; x++) {
                int jj = jh + x;
                float zi = z_sm[(0 * 8 + jj) * ZPAD + b] + pi[x];
                float zf = z_sm[(1 * 8 + jj) * ZPAD + b] + pf[x];
                float zg = z_sm[(2 * 8 + jj) * ZPAD + b] + pg[x];
                float zo = z_sm[(3 * 8 + jj) * ZPAD + b] + po[x];
                float ig = 1.f / (1.f + expf(-zi));
                float fg = 1.f / (1.f + expf(-zf));
                float og = 1.f / (1.f + expf(-zo));
                cn[x] = fg * co[x] + ig * tanhf(zg);
                hn[x] = og * tanhf(cn[x]);
            }
            *(float4*)cptr = make_float4(cn[0], cn[1], cn[2], cn[3]);
            *(float4*)(hs + ((size_t)tidx * BB + b) * H2 + (size_t)dir * HH + j0 + jh) =
                make_float4(hn[0], hn[1], hn[2], hn[3]);
            // publish tf32 bits for next step's mma
            uint4 ht = make_uint4(f2tf(hn[0]), f2tf(hn[1]), f2tf(hn[2]), f2tf(hn[3]));
            *(uint4*)(g_htf + ((size_t)dir * BB + b) * HH + j0 + jh) = ht;
        }

        // --- grid barrier ---
        if (s < TT - 1) {
            __threadfence();
            __syncthreads();
            if (tid == 0) {
                unsigned ticket = atomicAdd(&g_bar_count, 1u);
                if (ticket == NCTA - 1) {
                    g_bar_count = 0;
                    __threadfence();
                    atomicAdd(&g_bar_phase, 1u);
                } else {
                    unsigned target = phase0 + (unsigned)(s + 1);
                    while ((int)(*(volatile unsigned*)&g_bar_phase - target) < 0)
                        __nanosleep(32);
                }
                __threadfence();
            }
            __syncthreads();
        }
    }
}

// ---------------- 4) emissions (cls_w cached in SMEM, 9 sums in parallel) --------
__global__ void emis_kernel(const float* __restrict__ cls_w, const float* __restrict__ cls_b) {
    __shared__ float wsm[CC * H2];
    int tid = threadIdx.x;
    for (int i = tid; i < CC * H2; i += 256) wsm[i] = cls_w[i];
    __syncthreads();
    int warp = blockIdx.x * 8 + (tid >> 5);   // row = t*B+b
    int lane = tid & 31;
    const float* h = g_hs1 + (size_t)warp * H2;
    float sum[CC];
#pragma unroll
    for (int c = 0; c < CC; c++) sum[c] = 0.f;
    for (int k = lane; k < H2; k += 32) {
        float hk = h[k];
#pragma unroll
        for (int c = 0; c < CC; c++) sum[c] += hk * wsm[c * H2 + k];
    }
#pragma unroll
    for (int c = 0; c < CC; c++) {
        float sc = sum[c];
        for (int o = 16; o; o >>= 1) sc += __shfl_xor_sync(0xffffffffu, sc, o);
        if (lane == 0) g_emis[(size_t)warp * CC + c] = sc + cls_b[c];
    }
}

// ---------------- 5) CRF score + forward algorithm, one warp per batch -----------
__global__ void crf_kernel(const int* __restrict__ y,
                           const float* __restrict__ crf_start,
                           const float* __restrict__ crf_end,
                           const float* __restrict__ crf_trans) {
    int b = (blockIdx.x * blockDim.x + threadIdx.x) >> 5;
    int lane = threadIdx.x & 31;
    if (b >= BB) return;

    float local = 0.f; int cnt = 0;
    for (int t = lane; t < TT; t += 32) {
        int yt = y[b * TT + t];
        int tag = yt > 0 ? yt : 0;
        float e = g_emis[((size_t)t * BB + b) * CC + tag];
        if (t == 0) {
            local += crf_start[tag] + e;
        } else {
            int yp = y[b * TT + t - 1];
            int tp = yp > 0 ? yp : 0;
            float m = (yt > -1) ? 1.f : 0.f;
            local += m * (crf_trans[tp * CC + tag] + e);
        }
        cnt += (yt > -1) ? 1 : 0;
    }
    for (int o = 16; o; o >>= 1) {
        local += __shfl_xor_sync(0xffffffffu, local, o);
        cnt   += __shfl_xor_sync(0xffffffffu, cnt, o);
    }
    int seq_end = cnt - 1;
    int ylast = y[b * TT + seq_end];
    float score = local + crf_end[ylast > 0 ? ylast : 0];

    int j = lane < CC ? lane : (CC - 1);
    float tr[CC];
#pragma unroll
    for (int i = 0; i < CC; i++) tr[i] = crf_trans[i * CC + j];
    float alpha = crf_start[j] + g_emis[(size_t)b * CC + j];
    for (int t = 1; t < TT; t++) {
        float e = g_emis[((size_t)t * BB + b) * CC + j];
        float v[CC]; float m = -1e30f;
#pragma unroll
        for (int i = 0; i < CC; i++) {
            v[i] = __shfl_sync(0xffffffffu, alpha, i) + tr[i];
            m = fmaxf(m, v[i]);
        }
        float ssum = 0.f;
#pragma unroll
        for (int i = 0; i < CC; i++) ssum += expf(v[i] - m);
        float na = e + m + logf(ssum);
        bool mt = y[b * TT + t] > -1;
        alpha = mt ? na : alpha;
    }
    float val = (lane < CC) ? (alpha + crf_end[lane]) : -1e30f;
    float mm = val;
    for (int o = 16; o; o >>= 1) mm = fmaxf(mm, __shfl_xor_sync(0xffffffffu, mm, o));
    float se = expf(val - mm);
    for (int o = 16; o; o >>= 1) se += __shfl_xor_sync(0xffffffffu, se, o);
    float denom = mm + logf(se);
    if (lane == 0) g_llh[b] = score - denom;
}

// ---------------- 6) deterministic final reduction -------------------------------
__global__ void reduce_kernel(float* out) {
    __shared__ float sm[BB];
    int tid = threadIdx.x;
    sm[tid] = g_llh[tid];
    __syncthreads();
    for (int o = 64; o; o >>= 1) {
        if (tid < o) sm[tid] += sm[tid + o];
        __syncthreads();
    }
    if (tid == 0) out[0] = -sm[0] / (float)BB;
}

// ---------------- launch --------------------------------------------------------
extern "C" void kernel_launch(void* const* d_in, const int* in_sizes, int n_in,
                              void* d_out, int out_size) {
    (void)in_sizes; (void)n_in; (void)out_size;
    const int*   x         = (const int*)  d_in[0];
    const int*   y         = (const int*)  d_in[1];
    const float* embed     = (const float*)d_in[2];
    const float* w_ih_l0   = (const float*)d_in[3];
    const float* w_hh_l0   = (const float*)d_in[4];
    const float* b_l0      = (const float*)d_in[5];
    const float* w_ih_l1   = (const float*)d_in[6];
    const float* w_hh_l1   = (const float*)d_in[7];
    const float* b_l1      = (const float*)d_in[8];
    const float* cls_w     = (const float*)d_in[9];
    const float* cls_b     = (const float*)d_in[10];
    const float* crf_start = (const float*)d_in[11];
    const float* crf_end   = (const float*)d_in[12];
    const float* crf_trans = (const float*)d_in[13];
    float* out = (float*)d_out;

    // recurrent smem: wpack 4608 uint4 + hpack 4128 uint4 + z_sm
    const int SMEM_BYTES = (4608 + 4128) * 16 + 32 * ZPAD * 4;   // 156672
    static bool attr_set = false;
    if (!attr_set) {
        cudaFuncSetAttribute(recurrent_kernel<0>, cudaFuncAttributeMaxDynamicSharedMemorySize, SMEM_BYTES);
        cudaFuncSetAttribute(recurrent_kernel<1>, cudaFuncAttributeMaxDynamicSharedMemorySize, SMEM_BYTES);
        attr_set = true;
    }

    embed_kernel<<<TT * BB, 128>>>(x, embed);

    gemm_kernel<0><<<dim3(NN / 128, (TT * BB) / 128), 256>>>(w_ih_l0, b_l0);
    recurrent_kernel<0><<<NCTA, 256, SMEM_BYTES>>>(w_hh_l0);

    gemm_kernel<1><<<dim3(NN / 128, (TT * BB) / 128), 256>>>(w_ih_l1, b_l1);
    recurrent_kernel<1><<<NCTA, 256, SMEM_BYTES>>>(w_hh_l1);

    emis_kernel<<<(TT * BB) / 8, 256>>>(cls_w, cls_b);
    crf_kernel<<<16, 256>>>(y, crf_start, crf_end, crf_trans);
    reduce_kernel<<<1, 128>>>(out);
}

// round 5
// speedup vs baseline: 5.3667x; 1.0348x over previous
#include <cuda_runtime.h>
#include <math.h>

// Problem constants
#define TT 256
#define BB 128
#define HH 512
#define H2 1024   // 2H
#define G4 2048   // 4H
#define NN 4096   // 2 dirs * 4H
#define CC 9
#define NCTA 128
#define NCTA_DIR 64
#define ZPAD 132

// ---------------- scratch (device globals) ----------------
__device__ unsigned g_xstf[TT * BB * HH];      // tf32 bits of embedded input
__device__ float    g_pre [TT * BB * NN];
__device__ unsigned g_hs0tf[TT * BB * H2];     // tf32 bits of layer-0 output
__device__ float    g_hs1 [TT * BB * H2];
__device__ float    g_c   [2 * BB * HH];
__device__ unsigned g_htf [2][2 * BB * HH];    // tf32 h ping-pong by step parity
__device__ unsigned g_wtf [NN * H2];           // tf32 bits of current layer W_ih
__device__ float    g_emis[TT * BB * CC];
__device__ float    g_llh [BB];
__device__ unsigned g_bar_count2[2] = {0, 0};  // per-direction barrier
__device__ unsigned g_bar_phase2[2] = {0, 0};

// ---------------- helpers ----------------
__device__ __forceinline__ unsigned f2tf(float x) {
    unsigned u; asm("cvt.rna.tf32.f32 %0, %1;" : "=r"(u) : "f"(x)); return u;
}
__device__ __forceinline__ void mma_tf32(float* c, unsigned a0, unsigned a1,
                                         unsigned a2, unsigned a3,
                                         unsigned b0, unsigned b1) {
    asm volatile("mma.sync.aligned.m16n8k8.row.col.f32.tf32.tf32.f32 "
                 "{%0,%1,%2,%3}, {%4,%5,%6,%7}, {%8,%9}, {%0,%1,%2,%3};"
                 : "+f"(c[0]), "+f"(c[1]), "+f"(c[2]), "+f"(c[3])
                 : "r"(a0), "r"(a1), "r"(a2), "r"(a3), "r"(b0), "r"(b1));
}
__device__ __forceinline__ void cp16(unsigned dst_smem, const void* src) {
    asm volatile("cp.async.ca.shared.global [%0], [%1], 16;" :: "r"(dst_smem), "l"(src));
}
#define CP_COMMIT() asm volatile("cp.async.commit_group;")
#define CP_WAIT(n)  asm volatile("cp.async.wait_group %0;" :: "n"(n))

// ---------------- 1) embedding gather + maxnorm renorm -> tf32 bits --------------
__global__ void embed_kernel(const int* __restrict__ x, const float* __restrict__ embed) {
    int row = blockIdx.x;           // row = t*B + b
    int t = row / BB, b = row % BB;
    int tok = x[b * TT + t];
    const float* e = embed + (size_t)tok * HH;
    int tid = threadIdx.x;
    float v[4]; float ss = 0.f;
#pragma unroll
    for (int i = 0; i < 4; i++) { v[i] = e[tid + i * 128]; ss += v[i] * v[i]; }
    for (int o = 16; o; o >>= 1) ss += __shfl_xor_sync(0xffffffffu, ss, o);
    __shared__ float red[4];
    if ((tid & 31) == 0) red[tid >> 5] = ss;
    __syncthreads();
    float total = red[0] + red[1] + red[2] + red[3];
    float nrm = sqrtf(total);
    float sc = (nrm > 1.0f) ? 1.0f / (nrm + 1e-7f) : 1.0f;
    unsigned* dst = g_xstf + (size_t)row * HH;
#pragma unroll
    for (int i = 0; i < 4; i++) dst[tid + i * 128] = f2tf(v[i] * sc);
}

// ---------------- W_ih -> tf32 bits ----------------------------------------------
__global__ void cvtw_kernel(const float* __restrict__ W, int n4) {
    int i = blockIdx.x * 256 + threadIdx.x;
    if (i < n4) {
        float4 v = ((const float4*)W)[i];
        ((uint4*)g_wtf)[i] = make_uint4(f2tf(v.x), f2tf(v.y), f2tf(v.z), f2tf(v.w));
    }
}

// ---------------- 2) input projection GEMM (tf32, cp.async double-buffered) ------
// C(32768 x 4096) = A @ W^T + bias, inputs pre-converted to tf32 bits.
// CTA tile 128x128, BK=16, 2 stages. smem [row][k] stride 20 (conflict-free frags).
template <int K>
__global__ void __launch_bounds__(256) gemm_kernel(const unsigned* __restrict__ A,
                                                   const float* __restrict__ bias) {
    __shared__ unsigned a_s[2][128 * 20];
    __shared__ unsigned b_s[2][128 * 20];

    const unsigned* Wtf = g_wtf;
    const int m0 = blockIdx.y * 128, n0 = blockIdx.x * 128;
    const int tid = threadIdx.x;
    const int w = tid >> 5, lane = tid & 31;
    const int wm = w >> 2, wn = w & 3;
    const int lr = lane >> 2, lc = lane & 3;

    unsigned a_base = (unsigned)__cvta_generic_to_shared(a_s);
    unsigned b_base = (unsigned)__cvta_generic_to_shared(b_s);

    const int crow = tid >> 1;          // 0..127
    const int cq   = (tid & 1) * 2;     // copies float4 cq, cq+1

    float acc[4][4][4];
#pragma unroll
    for (int i = 0; i < 4; i++)
#pragma unroll
        for (int j = 0; j < 4; j++)
#pragma unroll
            for (int q = 0; q < 4; q++) acc[i][j][q] = 0.f;

    // stage(kt, st): copy 16-k slab starting at kt*16
    auto stage = [&](int kt, int st) {
        const unsigned* Arow = A + (size_t)(m0 + crow) * K + kt * 16;
        const unsigned* Wrow = Wtf + (size_t)(n0 + crow) * K + kt * 16;
        unsigned ad = a_base + (st * 128 * 20 + crow * 20 + cq * 4) * 4;
        unsigned bd = b_base + (st * 128 * 20 + crow * 20 + cq * 4) * 4;
        cp16(ad,      Arow + cq * 4);
        cp16(ad + 16, Arow + cq * 4 + 4);
        cp16(bd,      Wrow + cq * 4);
        cp16(bd + 16, Wrow + cq * 4 + 4);
    };

    stage(0, 0); CP_COMMIT();
    const int NT = K / 16;
    for (int kt = 0; kt < NT; kt++) {
        if (kt + 1 < NT) { stage(kt + 1, (kt + 1) & 1); CP_COMMIT(); CP_WAIT(1); }
        else             { CP_WAIT(0); }
        __syncthreads();
        const unsigned* As = a_s[kt & 1];
        const unsigned* Bs = b_s[kt & 1];
#pragma unroll
        for (int kk = 0; kk < 16; kk += 8) {
            unsigned af[4][4], bf[4][2];
#pragma unroll
            for (int mf = 0; mf < 4; mf++) {
                int r = wm * 64 + mf * 16 + lr;
                af[mf][0] = As[r * 20 + kk + lc];
                af[mf][1] = As[(r + 8) * 20 + kk + lc];
                af[mf][2] = As[r * 20 + kk + lc + 4];
                af[mf][3] = As[(r + 8) * 20 + kk + lc + 4];
            }
#pragma unroll
            for (int nf = 0; nf < 4; nf++) {
                int n = wn * 32 + nf * 8 + lr;
                bf[nf][0] = Bs[n * 20 + kk + lc];
                bf[nf][1] = Bs[n * 20 + kk + lc + 4];
            }
#pragma unroll
            for (int mf = 0; mf < 4; mf++)
#pragma unroll
                for (int nf = 0; nf < 4; nf++)
                    mma_tf32(acc[mf][nf], af[mf][0], af[mf][1], af[mf][2], af[mf][3],
                             bf[nf][0], bf[nf][1]);
        }
        __syncthreads();
    }
    // epilogue
#pragma unroll
    for (int nf = 0; nf < 4; nf++) {
        int col = n0 + wn * 32 + nf * 8 + 2 * lc;
        float b0v = bias[col], b1v = bias[col + 1];
#pragma unroll
        for (int mf = 0; mf < 4; mf++) {
            int row = m0 + wm * 64 + mf * 16 + lr;
            *(float2*)&g_pre[(size_t)row * NN + col] =
                make_float2(acc[mf][nf][0] + b0v, acc[mf][nf][1] + b1v);
            *(float2*)&g_pre[(size_t)(row + 8) * NN + col] =
                make_float2(acc[mf][nf][2] + b0v, acc[mf][nf][3] + b1v);
        }
    }
}

// ---------------- 3) persistent recurrent kernel (tf32 mma, cp.async, per-dir bar)
template <int L>
__global__ void __launch_bounds__(256, 1) recurrent_kernel(const float* __restrict__ w_hh) {
    extern __shared__ unsigned smu[];
    uint4* wpack = (uint4*)smu;               // [ks(64)][c(4)][half(2)] x 9
    uint4* hpack = wpack + 64 * 4 * 2 * 9;    // [2 bufs][q'(32)] x 129
    float* z_sm  = (float*)(hpack + 2 * 32 * 129);  // [32][ZPAD]

    const int tid = threadIdx.x;
    const int ct  = blockIdx.x;
    const int dir = ct >> 6;
    const int j0  = (ct & 63) * 8;
    const int w = tid >> 5, lane = tid & 31;
    const int wh = w >> 2, wn = w & 3;
    const int lr = lane >> 2, lc = lane & 3;

    unsigned phase0 = *(volatile unsigned*)&g_bar_phase2[dir];

    unsigned hp_base = (unsigned)__cvta_generic_to_shared(hpack);

    // --- pack resident weights into A-fragment layout (tf32) ---
#pragma unroll
    for (int i = 0; i < 16; i++) {
        int lin = tid + i * 256;             // 0..4095 over 32 rows x 128 float4
        int r  = lin >> 7;                   // local row = g*8+jj
        int k4 = lin & 127;
        const float* wr = w_hh + ((size_t)dir * G4 + (size_t)(r >> 3) * HH + j0 + (r & 7)) * HH + k4 * 4;
        float4 wv = *(const float4*)wr;
        unsigned vals[4] = {f2tf(wv.x), f2tf(wv.y), f2tf(wv.z), f2tf(wv.w)};
        int half = r >> 4, row = r & 7, ybit = (r >> 3) & 1;
#pragma unroll
        for (int j = 0; j < 4; j++) {
            int k = k4 * 4 + j;
            int ks = k >> 3, c = k & 3, kh = (k >> 2) & 1;
            ((unsigned*)&wpack[((ks * 4 + c) * 2 + half) * 9 + row])[ybit + 2 * kh] = vals[j];
        }
    }
    __syncthreads();

    const int pb  = tid >> 1;            // pointwise batch
    const int pjh = (tid & 1) * 4;       // pointwise j offset

    for (int s = 0; s < TT; s++) {
        const int tidx = dir ? (TT - 1 - s) : s;

        // --- prefetch pointwise operands (independent of h/mma) ---
        const float* p = g_pre + ((size_t)tidx * BB + pb) * NN + (size_t)dir * G4;
        float4 p0 = *(const float4*)(p + 0 * HH + j0 + pjh);
        float4 p1 = *(const float4*)(p + 1 * HH + j0 + pjh);
        float4 p2 = *(const float4*)(p + 2 * HH + j0 + pjh);
        float4 p3 = *(const float4*)(p + 3 * HH + j0 + pjh);
        float* cptr = g_c + ((size_t)dir * BB + pb) * HH + j0 + pjh;
        float4 cold = (s == 0) ? make_float4(0.f, 0.f, 0.f, 0.f) : *(float4*)cptr;

        float acc[4][4];
#pragma unroll
        for (int nf = 0; nf < 4; nf++)
#pragma unroll
            for (int q = 0; q < 4; q++) acc[nf][q] = 0.f;

        if (s > 0) {
            const unsigned* hsrc = g_htf[s & 1] + (size_t)dir * BB * HH;
            // stage(kc, buf): 16 cp16 per thread (4096 uint4 total)
            auto stageh = [&](int kc, int buf) {
#pragma unroll
                for (int i = 0; i < 16; i++) {
                    int lin = tid + i * 256;
                    int b = lin >> 5, q = lin & 31;
                    cp16(hp_base + (unsigned)(buf * 4128 + q * 129 + b) * 16,
                         hsrc + (size_t)b * HH + kc * 128 + q * 4);
                }
            };
            stageh(0, 0); CP_COMMIT();
#pragma unroll
            for (int kc = 0; kc < 4; kc++) {
                if (kc < 3) { stageh(kc + 1, (kc + 1) & 1); CP_COMMIT(); CP_WAIT(1); }
                else        { CP_WAIT(0); }
                __syncthreads();
                const uint4* hp = hpack + (kc & 1) * 4128;
#pragma unroll
                for (int ls = 0; ls < 16; ls++) {
                    int ks = kc * 16 + ls;
                    uint4 aa = wpack[((ks * 4 + lc) * 2 + wh) * 9 + lr];
#pragma unroll
                    for (int nf = 0; nf < 4; nf++) {
                        int b = wn * 32 + nf * 8 + lr;
                        unsigned b0 = ((const unsigned*)&hp[(ls * 2 + 0) * 129 + b])[lc];
                        unsigned b1 = ((const unsigned*)&hp[(ls * 2 + 1) * 129 + b])[lc];
                        mma_tf32(acc[nf], aa.x, aa.y, aa.z, aa.w, b0, b1);
                    }
                }
                __syncthreads();
            }
        }

        // --- z exchange ---
#pragma unroll
        for (int nf = 0; nf < 4; nf++) {
            int row = wh * 16 + lr;
            int col = wn * 32 + nf * 8 + 2 * lc;
            *(float2*)&z_sm[row * ZPAD + col]       = make_float2(acc[nf][0], acc[nf][1]);
            *(float2*)&z_sm[(row + 8) * ZPAD + col] = make_float2(acc[nf][2], acc[nf][3]);
        }
        __syncthreads();

        // --- fused LSTM pointwise ---
        {
            float pi[4] = {p0.x, p0.y, p0.z, p0.w};
            float pf[4] = {p1.x, p1.y, p1.z, p1.w};
            float pg[4] = {p2.x, p2.y, p2.z, p2.w};
            float po[4] = {p3.x, p3.y, p3.z, p3.w};
            float co[4] = {cold.x, cold.y, cold.z, cold.w};
            float hn[4], cn[4];
#pragma unroll
            for (int x = 0; x < 4; x++) {
                int jj = pjh + x;
                float zi = z_sm[(0 * 8 + jj) * ZPAD + pb] + pi[x];
                float zf = z_sm[(1 * 8 + jj) * ZPAD + pb] + pf[x];
                float zg = z_sm[(2 * 8 + jj) * ZPAD + pb] + pg[x];
                float zo = z_sm[(3 * 8 + jj) * ZPAD + pb] + po[x];
                float ig = 1.f / (1.f + expf(-zi));
                float fg = 1.f / (1.f + expf(-zf));
                float og = 1.f / (1.f + expf(-zo));
                cn[x] = fg * co[x] + ig * tanhf(zg);
                hn[x] = og * tanhf(cn[x]);
            }
            *(float4*)cptr = make_float4(cn[0], cn[1], cn[2], cn[3]);
            uint4 ht = make_uint4(f2tf(hn[0]), f2tf(hn[1]), f2tf(hn[2]), f2tf(hn[3]));
            // ping-pong publish for next step's mma
            *(uint4*)(g_htf[(s + 1) & 1] + ((size_t)dir * BB + pb) * HH + j0 + pjh) = ht;
            if (L == 0) {
                *(uint4*)(g_hs0tf + ((size_t)tidx * BB + pb) * H2 + (size_t)dir * HH + j0 + pjh) = ht;
            } else {
                *(float4*)(g_hs1 + ((size_t)tidx * BB + pb) * H2 + (size_t)dir * HH + j0 + pjh) =
                    make_float4(hn[0], hn[1], hn[2], hn[3]);
            }
        }

        // --- per-direction grid barrier ---
        if (s < TT - 1) {
            __threadfence();
            __syncthreads();
            if (tid == 0) {
                unsigned ticket = atomicAdd(&g_bar_count2[dir], 1u);
                if (ticket == NCTA_DIR - 1) {
                    g_bar_count2[dir] = 0;
                    __threadfence();
                    atomicAdd(&g_bar_phase2[dir], 1u);
                } else {
                    unsigned target = phase0 + (unsigned)(s + 1);
                    while ((int)(*(volatile unsigned*)&g_bar_phase2[dir] - target) < 0)
                        __nanosleep(32);
                }
                __threadfence();
            }
            __syncthreads();
        }
    }
}

// ---------------- 4) emissions (cls_w cached in SMEM) ----------------------------
__global__ void emis_kernel(const float* __restrict__ cls_w, const float* __restrict__ cls_b) {
    __shared__ float wsm[CC * H2];
    int tid = threadIdx.x;
    for (int i = tid; i < CC * H2; i += 256) wsm[i] = cls_w[i];
    __syncthreads();
    int warp = blockIdx.x * 8 + (tid >> 5);
    int lane = tid & 31;
    const float* h = g_hs1 + (size_t)warp * H2;
    float sum[CC];
#pragma unroll
    for (int c = 0; c < CC; c++) sum[c] = 0.f;
    for (int k = lane; k < H2; k += 32) {
        float hk = h[k];
#pragma unroll
        for (int c = 0; c < CC; c++) sum[c] += hk * wsm[c * H2 + k];
    }
#pragma unroll
    for (int c = 0; c < CC; c++) {
        float sc = sum[c];
        for (int o = 16; o; o >>= 1) sc += __shfl_xor_sync(0xffffffffu, sc, o);
        if (lane == 0) g_emis[(size_t)warp * CC + c] = sc + cls_b[c];
    }
}

// ---------------- 5) CRF score + forward algorithm, one warp per batch -----------
__global__ void crf_kernel(const int* __restrict__ y,
                           const float* __restrict__ crf_start,
                           const float* __restrict__ crf_end,
                           const float* __restrict__ crf_trans) {
    int b = (blockIdx.x * blockDim.x + threadIdx.x) >> 5;
    int lane = threadIdx.x & 31;
    if (b >= BB) return;

    float local = 0.f; int cnt = 0;
    for (int t = lane; t < TT; t += 32) {
        int yt = y[b * TT + t];
        int tag = yt > 0 ? yt : 0;
        float e = g_emis[((size_t)t * BB + b) * CC + tag];
        if (t == 0) {
            local += crf_start[tag] + e;
        } else {
            int yp = y[b * TT + t - 1];
            int tp = yp > 0 ? yp : 0;
            float m = (yt > -1) ? 1.f : 0.f;
            local += m * (crf_trans[tp * CC + tag] + e);
        }
        cnt += (yt > -1) ? 1 : 0;
    }
    for (int o = 16; o; o >>= 1) {
        local += __shfl_xor_sync(0xffffffffu, local, o);
        cnt   += __shfl_xor_sync(0xffffffffu, cnt, o);
    }
    int seq_end = cnt - 1;
    int ylast = y[b * TT + seq_end];
    float score = local + crf_end[ylast > 0 ? ylast : 0];

    int j = lane < CC ? lane : (CC - 1);
    float tr[CC];
#pragma unroll
    for (int i = 0; i < CC; i++) tr[i] = crf_trans[i * CC + j];
    float alpha = crf_start[j] + g_emis[(size_t)b * CC + j];
    for (int t = 1; t < TT; t++) {
        float e = g_emis[((size_t)t * BB + b) * CC + j];
        float v[CC]; float m = -1e30f;
#pragma unroll
        for (int i = 0; i < CC; i++) {
            v[i] = __shfl_sync(0xffffffffu, alpha, i) + tr[i];
            m = fmaxf(m, v[i]);
        }
        float ssum = 0.f;
#pragma unroll
        for (int i = 0; i < CC; i++) ssum += expf(v[i] - m);
        float na = e + m + logf(ssum);
        bool mt = y[b * TT + t] > -1;
        alpha = mt ? na : alpha;
    }
    float val = (lane < CC) ? (alpha + crf_end[lane]) : -1e30f;
    float mm = val;
    for (int o = 16; o; o >>= 1) mm = fmaxf(mm, __shfl_xor_sync(0xffffffffu, mm, o));
    float se = expf(val - mm);
    for (int o = 16; o; o >>= 1) se += __shfl_xor_sync(0xffffffffu, se, o);
    float denom = mm + logf(se);
    if (lane == 0) g_llh[b] = score - denom;
}

// ---------------- 6) deterministic final reduction -------------------------------
__global__ void reduce_kernel(float* out) {
    __shared__ float sm[BB];
    int tid = threadIdx.x;
    sm[tid] = g_llh[tid];
    __syncthreads();
    for (int o = 64; o; o >>= 1) {
        if (tid < o) sm[tid] += sm[tid + o];
        __syncthreads();
    }
    if (tid == 0) out[0] = -sm[0] / (float)BB;
}

// ---------------- launch --------------------------------------------------------
extern "C" void kernel_launch(void* const* d_in, const int* in_sizes, int n_in,
                              void* d_out, int out_size) {
    (void)in_sizes; (void)n_in; (void)out_size;
    const int*   x         = (const int*)  d_in[0];
    const int*   y         = (const int*)  d_in[1];
    const float* embed     = (const float*)d_in[2];
    const float* w_ih_l0   = (const float*)d_in[3];
    const float* w_hh_l0   = (const float*)d_in[4];
    const float* b_l0      = (const float*)d_in[5];
    const float* w_ih_l1   = (const float*)d_in[6];
    const float* w_hh_l1   = (const float*)d_in[7];
    const float* b_l1      = (const float*)d_in[8];
    const float* cls_w     = (const float*)d_in[9];
    const float* cls_b     = (const float*)d_in[10];
    const float* crf_start = (const float*)d_in[11];
    const float* crf_end   = (const float*)d_in[12];
    const float* crf_trans = (const float*)d_in[13];
    float* out = (float*)d_out;

    // recurrent smem: wpack 4608 uint4 + hpack 2*4128 uint4 + z_sm
    const int SMEM_BYTES = (4608 + 2 * 4128) * 16 + 32 * ZPAD * 4;   // 222720
    static bool attr_set = false;
    if (!attr_set) {
        cudaFuncSetAttribute(recurrent_kernel<0>, cudaFuncAttributeMaxDynamicSharedMemorySize, SMEM_BYTES);
        cudaFuncSetAttribute(recurrent_kernel<1>, cudaFuncAttributeMaxDynamicSharedMemorySize, SMEM_BYTES);
        attr_set = true;
    }

    unsigned* xstf;  cudaGetSymbolAddress((void**)&xstf,  g_xstf);
    unsigned* hs0tf; cudaGetSymbolAddress((void**)&hs0tf, g_hs0tf);

    embed_kernel<<<TT * BB, 128>>>(x, embed);

    cvtw_kernel<<<(NN * HH / 4 + 255) / 256, 256>>>(w_ih_l0, NN * HH / 4);
    gemm_kernel<HH><<<dim3(NN / 128, (TT * BB) / 128), 256>>>(xstf, b_l0);
    recurrent_kernel<0><<<NCTA, 256, SMEM_BYTES>>>(w_hh_l0);

    cvtw_kernel<<<(NN * H2 / 4 + 255) / 256, 256>>>(w_ih_l1, NN * H2 / 4);
    gemm_kernel<H2><<<dim3(NN / 128, (TT * BB) / 128), 256>>>(hs0tf, b_l1);
    recurrent_kernel<1><<<NCTA, 256, SMEM_BYTES>>>(w_hh_l1);

    emis_kernel<<<(TT * BB) / 8, 256>>>(cls_w, cls_b);
    crf_kernel<<<16, 256>>>(y, crf_start, crf_end, crf_trans);
    reduce_kernel<<<1, 128>>>(out);
}

// round 7
// speedup vs baseline: 6.0426x; 1.1260x over previous
#include <cuda_runtime.h>
#include <math.h>

// Problem constants
#define TT 256
#define BB 128
#define HH 512
#define H2 1024   // 2H
#define G4 2048   // 4H
#define NN 4096   // 2 dirs * 4H
#define CC 9
#define NCTA 128
#define NCTA_DIR 64
#define ZPAD 132

// ============ fragment-permuted global layouts =================================
// A-perm (mma A operand, 16(m)x8(k) tiles): element (m,k) ->
//   mt=m/16, kt=k/8, r=m%16, c=k%8, lane=(r&7)*4+(c&3), word=(r>>3)+2*(c>>2);
//   flat = ((mt*KT+kt)*32+lane)*4+word
// B-perm (mma B operand, 8(n)x8(k) tiles): element (n,k) ->
//   nt=n/8, kt=k/8, lane=(n&7)*4+(k&3), word=(k>>2)&1;
//   flat = ((nt*KT+kt)*32+lane)*2+word

// ---------------- scratch (device globals) ----------------
__device__ unsigned g_xstf [TT * BB * HH];    // A-perm input (K=512)
__device__ float    g_pre  [TT * BB * NN];
__device__ unsigned g_hs0tf[TT * BB * H2];    // A-perm layer-0 output (K=1024)
__device__ float    g_hs1  [TT * BB * H2];
__device__ float    g_c    [2 * BB * HH];
__device__ unsigned g_htf  [2][2 * 65536];    // B-perm h, [parity][dir*65536]
__device__ unsigned g_wtf  [NN * H2];         // B-perm W_ih of current layer
__device__ float    g_emis [TT * BB * CC];
__device__ float    g_llh  [BB];
__device__ unsigned g_bar_count2[2] = {0, 0};
__device__ unsigned g_bar_phase2[2] = {0, 0};

// ---------------- helpers ----------------
__device__ __forceinline__ unsigned f2tf(float x) {
    unsigned u; asm("cvt.rna.tf32.f32 %0, %1;" : "=r"(u) : "f"(x)); return u;
}
__device__ __forceinline__ void mma_tf32(float* c, unsigned a0, unsigned a1,
                                         unsigned a2, unsigned a3,
                                         unsigned b0, unsigned b1) {
    asm volatile("mma.sync.aligned.m16n8k8.row.col.f32.tf32.tf32.f32 "
                 "{%0,%1,%2,%3}, {%4,%5,%6,%7}, {%8,%9}, {%0,%1,%2,%3};"
                 : "+f"(c[0]), "+f"(c[1]), "+f"(c[2]), "+f"(c[3])
                 : "r"(a0), "r"(a1), "r"(a2), "r"(a3), "r"(b0), "r"(b1));
}
__device__ __forceinline__ void cp16(unsigned dst_smem, const void* src) {
    asm volatile("cp.async.ca.shared.global [%0], [%1], 16;" :: "r"(dst_smem), "l"(src));
}
#define CP_COMMIT() asm volatile("cp.async.commit_group;")
#define CP_WAIT(n)  asm volatile("cp.async.wait_group %0;" :: "n"(n))

// ---------------- 1) embedding gather + renorm -> A-perm tf32 --------------------
__global__ void embed_kernel(const int* __restrict__ x, const float* __restrict__ embed) {
    int row = blockIdx.x;           // m = t*B + b
    int t = row / BB, b = row % BB;
    int tok = x[b * TT + t];
    const float* e = embed + (size_t)tok * HH;
    int tid = threadIdx.x;
    float v[4]; float ss = 0.f;
#pragma unroll
    for (int i = 0; i < 4; i++) { v[i] = e[tid + i * 128]; ss += v[i] * v[i]; }
    for (int o = 16; o; o >>= 1) ss += __shfl_xor_sync(0xffffffffu, ss, o);
    __shared__ float red[4];
    if ((tid & 31) == 0) red[tid >> 5] = ss;
    __syncthreads();
    float total = red[0] + red[1] + red[2] + red[3];
    float nrm = sqrtf(total);
    float sc = (nrm > 1.0f) ? 1.0f / (nrm + 1e-7f) : 1.0f;
    int mt = row >> 4, r = row & 15;
    unsigned lbase = (unsigned)((r & 7) * 4);
    unsigned wr = (unsigned)(r >> 3);
#pragma unroll
    for (int i = 0; i < 4; i++) {
        int k = tid + i * 128;
        int kt = k >> 3, c = k & 7;
        unsigned lane = lbase + (c & 3);
        unsigned word = wr + 2 * (c >> 2);
        g_xstf[(((size_t)mt * 64 + kt) * 32 + lane) * 4 + word] = f2tf(v[i] * sc);
    }
}

// ---------------- W_ih -> B-perm tf32 bits ---------------------------------------
__global__ void cvtw_kernel(const float* __restrict__ W, int K) {
    int i = blockIdx.x * 256 + threadIdx.x;       // over NN*(K/4)
    int kq = K >> 2;
    if (i >= NN * kq) return;
    int n = i / kq, q = i - n * kq;
    float4 v = *(const float4*)(W + (size_t)n * K + q * 4);
    unsigned vals[4] = {f2tf(v.x), f2tf(v.y), f2tf(v.z), f2tf(v.w)};
    int nt = n >> 3, kt = q >> 1, word = q & 1;
    size_t base = (((size_t)nt * (K >> 3) + kt) * 32 + (n & 7) * 4) * 2 + word;
#pragma unroll
    for (int j = 0; j < 4; j++) g_wtf[base + j * 2] = vals[j];
}

// ---------------- 2) input projection GEMM (perm layouts, 3-stage cp.async) ------
// C(32768 x 4096) = A @ W^T + bias. CTA tile 128x128 (8 m-tiles x 16 n-tiles),
// slab = 16 k (2 k-tiles), 3-stage pipeline, all fragment loads LDS.128/LDS.64.
template <int K>
__global__ void __launch_bounds__(256) gemm_kernel(const unsigned* __restrict__ A,
                                                   const float* __restrict__ bias) {
    __shared__ unsigned a_s[3][2048];
    __shared__ unsigned b_s[3][2048];   // 16 nt x 2 kt x 64 words = 2048 (R6 bug: was 1024)

    constexpr int KT = K >> 3;
    const int mt0 = blockIdx.y * 8, nt0 = blockIdx.x * 16;
    const int tid = threadIdx.x;
    const int w = tid >> 5, lane = tid & 31;
    const int wm = w >> 2, wn = w & 3;
    const int lr = lane >> 2, lc = lane & 3;

    unsigned a_base = (unsigned)__cvta_generic_to_shared(a_s);
    unsigned b_base = (unsigned)__cvta_generic_to_shared(b_s);

    float acc[4][4][4];
#pragma unroll
    for (int i = 0; i < 4; i++)
#pragma unroll
        for (int j = 0; j < 4; j++)
#pragma unroll
            for (int q = 0; q < 4; q++) acc[i][j][q] = 0.f;

    // stage slab 'sl' (2 k-tiles at kt0 = sl*2) into buffer st
    auto stage = [&](int sl, int st) {
        int kt0 = sl * 2;
#pragma unroll
        for (int rep = 0; rep < 2; rep++) {
            int c = tid + rep * 256;              // 0..511
            // A: mtl = c>>6, ktl = (c>>5)&1, q = c&31  (8 mt x 2 kt x 32 float4)
            {
                int mtl = c >> 6, ktl = (c >> 5) & 1, q = c & 31;
                const unsigned* src = A + (((size_t)(mt0 + mtl) * KT + kt0 + ktl) * 128 + q * 4);
                cp16(a_base + (st * 2048 + (mtl * 2 + ktl) * 128 + q * 4) * 4, src);
            }
            // B: ntl = c>>5, ktl = (c>>4)&1, q = c&15  (16 nt x 2 kt x 16 float4)
            {
                int ntl = c >> 5, ktl = (c >> 4) & 1, q = c & 15;
                const unsigned* src = g_wtf + (((size_t)(nt0 + ntl) * KT + kt0 + ktl) * 64 + q * 4);
                cp16(b_base + (st * 2048 + (ntl * 2 + ktl) * 64 + q * 4) * 4, src);
            }
        }
    };

    constexpr int NS = KT / 2;          // number of slabs
    stage(0, 0); CP_COMMIT();
    stage(1, 1); CP_COMMIT();
    int buf = 0;
    for (int it = 0; it < NS; it++) {
        if (it + 1 < NS) CP_WAIT(1); else CP_WAIT(0);
        __syncthreads();
        const unsigned* As = a_s[buf];
        const unsigned* Bs = b_s[buf];
#pragma unroll
        for (int ktl = 0; ktl < 2; ktl++) {
            uint4 af[4]; uint2 bf[4];
#pragma unroll
            for (int mf = 0; mf < 4; mf++)
                af[mf] = *(const uint4*)&As[((wm * 4 + mf) * 2 + ktl) * 128 + lane * 4];
#pragma unroll
            for (int nf = 0; nf < 4; nf++)
                bf[nf] = *(const uint2*)&Bs[((wn * 4 + nf) * 2 + ktl) * 64 + lane * 2];
#pragma unroll
            for (int mf = 0; mf < 4; mf++)
#pragma unroll
                for (int nf = 0; nf < 4; nf++)
                    mma_tf32(acc[mf][nf], af[mf].x, af[mf].y, af[mf].z, af[mf].w,
                             bf[nf].x, bf[nf].y);
        }
        __syncthreads();
        if (it + 2 < NS) { stage(it + 2, (buf + 2) % 3); CP_COMMIT(); }
        buf = (buf + 1) % 3;
    }
    // epilogue
    const int m0 = mt0 * 16, n0 = nt0 * 8;
#pragma unroll
    for (int nf = 0; nf < 4; nf++) {
        int col = n0 + wn * 32 + nf * 8 + 2 * lc;
        float b0v = bias[col], b1v = bias[col + 1];
#pragma unroll
        for (int mf = 0; mf < 4; mf++) {
            int row = m0 + wm * 64 + mf * 16 + lr;
            *(float2*)&g_pre[(size_t)row * NN + col] =
                make_float2(acc[mf][nf][0] + b0v, acc[mf][nf][1] + b1v);
            *(float2*)&g_pre[(size_t)(row + 8) * NN + col] =
                make_float2(acc[mf][nf][2] + b0v, acc[mf][nf][3] + b1v);
        }
    }
}

// ---------------- 3) persistent recurrent kernel (perm layouts) ------------------
// CTA ct: dir = ct>>6, j0 = (ct&63)*8 -> 32 z rows (2 mma m-tiles) resident in
// SMEM (A-perm). h in g_htf (B-perm per dir), staged by chunks of 128 k.
template <int L>
__global__ void __launch_bounds__(256, 1) recurrent_kernel(const float* __restrict__ w_hh) {
    extern __shared__ unsigned smu[];
    unsigned* wpack = smu;                    // [mt(2)][kt(64)][lane(32)][4] = 16384
    unsigned* hpk   = smu + 16384;            // 2 bufs x [nt(16)][ktl(16)][lane(32)][2] = 2*16384
    float* z_sm = (float*)(smu + 16384 + 32768);  // [32][ZPAD]

    const int tid = threadIdx.x;
    const int ct  = blockIdx.x;
    const int dir = ct >> 6;
    const int j0  = (ct & 63) * 8;
    const int w = tid >> 5, lane = tid & 31;
    const int wh = w >> 2, wn = w & 3;
    const int lr = lane >> 2, lc = lane & 3;

    unsigned phase0 = *(volatile unsigned*)&g_bar_phase2[dir];
    unsigned hp_base = (unsigned)__cvta_generic_to_shared(hpk);

    // --- pack resident weights (A-perm, rows r32 = g*8+jj) ---
#pragma unroll
    for (int i = 0; i < 16; i++) {
        int lin = tid + i * 256;             // 32 rows x 128 float4
        int r32 = lin >> 7, k4 = lin & 127;
        const float* wr = w_hh + ((size_t)dir * G4 + (size_t)(r32 >> 3) * HH + j0 + (r32 & 7)) * HH + k4 * 4;
        float4 wv = *(const float4*)wr;
        unsigned vals[4] = {f2tf(wv.x), f2tf(wv.y), f2tf(wv.z), f2tf(wv.w)};
        int mt = r32 >> 4, r = r32 & 15;
        int kt = k4 >> 1;
        unsigned lane0 = (unsigned)((r & 7) * 4);
        unsigned word = (unsigned)((r >> 3) + 2 * (k4 & 1));
#pragma unroll
        for (int j = 0; j < 4; j++)
            wpack[((mt * 64 + kt) * 32 + lane0 + j) * 4 + word] = vals[j];
    }
    __syncthreads();

    const int pb  = tid >> 1;            // pointwise batch
    const int pjh = (tid & 1) * 4;       // pointwise j offset (0 or 4)

    for (int s = 0; s < TT; s++) {
        const int tidx = dir ? (TT - 1 - s) : s;

        // --- prefetch pointwise operands ---
        const float* p = g_pre + ((size_t)tidx * BB + pb) * NN + (size_t)dir * G4;
        float4 p0 = *(const float4*)(p + 0 * HH + j0 + pjh);
        float4 p1 = *(const float4*)(p + 1 * HH + j0 + pjh);
        float4 p2 = *(const float4*)(p + 2 * HH + j0 + pjh);
        float4 p3 = *(const float4*)(p + 3 * HH + j0 + pjh);
        float* cptr = g_c + ((size_t)dir * BB + pb) * HH + j0 + pjh;
        float4 cold = (s == 0) ? make_float4(0.f, 0.f, 0.f, 0.f) : *(float4*)cptr;

        float acc[4][4];
#pragma unroll
        for (int nf = 0; nf < 4; nf++)
#pragma unroll
            for (int q = 0; q < 4; q++) acc[nf][q] = 0.f;

        if (s > 0) {
            const unsigned* hsrc = g_htf[s & 1] + dir * 65536;
            // stage chunk kc (16 k-tiles): straight contiguous copy per n-tile
            auto stageh = [&](int kc, int buf) {
#pragma unroll
                for (int i = 0; i < 16; i++) {
                    int c = tid + i * 256;            // 0..4095
                    int nt = c >> 8, off = (c & 255) * 4;
                    cp16(hp_base + (unsigned)(buf * 16384 + nt * 1024 + off) * 4,
                         hsrc + ((size_t)nt * 64 + kc * 16) * 64 + off);
                }
            };
            stageh(0, 0); CP_COMMIT();
#pragma unroll
            for (int kc = 0; kc < 4; kc++) {
                if (kc < 3) { stageh(kc + 1, (kc + 1) & 1); CP_COMMIT(); CP_WAIT(1); }
                else        { CP_WAIT(0); }
                __syncthreads();
                const unsigned* hp = hpk + (kc & 1) * 16384;
#pragma unroll
                for (int ls = 0; ls < 16; ls++) {
                    int ks = kc * 16 + ls;
                    uint4 aa = *(const uint4*)&wpack[((wh * 64 + ks) * 32 + lane) * 4];
#pragma unroll
                    for (int nf = 0; nf < 4; nf++) {
                        uint2 bb = *(const uint2*)&hp[(wn * 4 + nf) * 1024 + ls * 64 + lane * 2];
                        mma_tf32(acc[nf], aa.x, aa.y, aa.z, aa.w, bb.x, bb.y);
                    }
                }
                __syncthreads();
            }
        }

        // --- z exchange ---
#pragma unroll
        for (int nf = 0; nf < 4; nf++) {
            int row = wh * 16 + lr;
            int col = wn * 32 + nf * 8 + 2 * lc;
            *(float2*)&z_sm[row * ZPAD + col]       = make_float2(acc[nf][0], acc[nf][1]);
            *(float2*)&z_sm[(row + 8) * ZPAD + col] = make_float2(acc[nf][2], acc[nf][3]);
        }
        __syncthreads();

        // --- fused LSTM pointwise ---
        {
            float pi[4] = {p0.x, p0.y, p0.z, p0.w};
            float pf[4] = {p1.x, p1.y, p1.z, p1.w};
            float pg[4] = {p2.x, p2.y, p2.z, p2.w};
            float po[4] = {p3.x, p3.y, p3.z, p3.w};
            float co[4] = {cold.x, cold.y, cold.z, cold.w};
            float hn[4], cn[4];
            unsigned ht[4];
#pragma unroll
            for (int x = 0; x < 4; x++) {
                int jj = pjh + x;
                float zi = z_sm[(0 * 8 + jj) * ZPAD + pb] + pi[x];
                float zf = z_sm[(1 * 8 + jj) * ZPAD + pb] + pf[x];
                float zg = z_sm[(2 * 8 + jj) * ZPAD + pb] + pg[x];
                float zo = z_sm[(3 * 8 + jj) * ZPAD + pb] + po[x];
                float ig = 1.f / (1.f + expf(-zi));
                float fg = 1.f / (1.f + expf(-zf));
                float og = 1.f / (1.f + expf(-zo));
                cn[x] = fg * co[x] + ig * tanhf(zg);
                hn[x] = og * tanhf(cn[x]);
                ht[x] = f2tf(hn[x]);
            }
            *(float4*)cptr = make_float4(cn[0], cn[1], cn[2], cn[3]);

            // publish h in B-perm for next step: (n=pb, k=j0+pjh+x)
            unsigned* hd = g_htf[(s + 1) & 1] + dir * 65536;
            {
                int nt = pb >> 3, kt = j0 >> 3;
                unsigned base = ((unsigned)(nt * 64 + kt) * 32 + (pb & 7) * 4) * 2 + (pjh >> 2);
#pragma unroll
                for (int x = 0; x < 4; x++) hd[base + x * 2] = ht[x];
            }
            if (L == 0) {
                // publish hs0 in A-perm (K=1024) for GEMM1: (m=tidx*128+pb, k=dir*512+j0+pjh+x)
                int m = tidx * BB + pb;
                int mt = m >> 4, r = m & 15;
                int kt = (dir * HH + j0 + pjh) >> 3;
                unsigned word = (unsigned)((r >> 3) + 2 * (pjh >> 2));
                size_t base = (((size_t)mt * 128 + kt) * 32 + (r & 7) * 4) * 4 + word;
#pragma unroll
                for (int x = 0; x < 4; x++) g_hs0tf[base + x * 4] = ht[x];
            } else {
                *(float4*)(g_hs1 + ((size_t)tidx * BB + pb) * H2 + (size_t)dir * HH + j0 + pjh) =
                    make_float4(hn[0], hn[1], hn[2], hn[3]);
            }
        }

        // --- per-direction grid barrier ---
        if (s < TT - 1) {
            __threadfence();
            __syncthreads();
            if (tid == 0) {
                unsigned ticket = atomicAdd(&g_bar_count2[dir], 1u);
                if (ticket == NCTA_DIR - 1) {
                    g_bar_count2[dir] = 0;
                    __threadfence();
                    atomicAdd(&g_bar_phase2[dir], 1u);
                } else {
                    unsigned target = phase0 + (unsigned)(s + 1);
                    while ((int)(*(volatile unsigned*)&g_bar_phase2[dir] - target) < 0)
                        __nanosleep(32);
                }
                __threadfence();
            }
            __syncthreads();
        }
    }
}

// ---------------- 4) emissions (cls_w cached in SMEM) ----------------------------
__global__ void emis_kernel(const float* __restrict__ cls_w, const float* __restrict__ cls_b) {
    __shared__ float wsm[CC * H2];
    int tid = threadIdx.x;
    for (int i = tid; i < CC * H2; i += 256) wsm[i] = cls_w[i];
    __syncthreads();
    int warp = blockIdx.x * 8 + (tid >> 5);
    int lane = tid & 31;
    const float* h = g_hs1 + (size_t)warp * H2;
    float sum[CC];
#pragma unroll
    for (int c = 0; c < CC; c++) sum[c] = 0.f;
    for (int k = lane; k < H2; k += 32) {
        float hk = h[k];
#pragma unroll
        for (int c = 0; c < CC; c++) sum[c] += hk * wsm[c * H2 + k];
    }
#pragma unroll
    for (int c = 0; c < CC; c++) {
        float sc = sum[c];
        for (int o = 16; o; o >>= 1) sc += __shfl_xor_sync(0xffffffffu, sc, o);
        if (lane == 0) g_emis[(size_t)warp * CC + c] = sc + cls_b[c];
    }
}

// ---------------- 5) CRF score + forward algorithm, one warp per batch -----------
__global__ void crf_kernel(const int* __restrict__ y,
                           const float* __restrict__ crf_start,
                           const float* __restrict__ crf_end,
                           const float* __restrict__ crf_trans) {
    int b = (blockIdx.x * blockDim.x + threadIdx.x) >> 5;
    int lane = threadIdx.x & 31;
    if (b >= BB) return;

    float local = 0.f; int cnt = 0;
    for (int t = lane; t < TT; t += 32) {
        int yt = y[b * TT + t];
        int tag = yt > 0 ? yt : 0;
        float e = g_emis[((size_t)t * BB + b) * CC + tag];
        if (t == 0) {
            local += crf_start[tag] + e;
        } else {
            int yp = y[b * TT + t - 1];
            int tp = yp > 0 ? yp : 0;
            float m = (yt > -1) ? 1.f : 0.f;
            local += m * (crf_trans[tp * CC + tag] + e);
        }
        cnt += (yt > -1) ? 1 : 0;
    }
    for (int o = 16; o; o >>= 1) {
        local += __shfl_xor_sync(0xffffffffu, local, o);
        cnt   += __shfl_xor_sync(0xffffffffu, cnt, o);
    }
    int seq_end = cnt - 1;
    int ylast = y[b * TT + seq_end];
    float score = local + crf_end[ylast > 0 ? ylast : 0];

    int j = lane < CC ? lane : (CC - 1);
    float tr[CC];
#pragma unroll
    for (int i = 0; i < CC; i++) tr[i] = crf_trans[i * CC + j];
    float alpha = crf_start[j] + g_emis[(size_t)b * CC + j];
    for (int t = 1; t < TT; t++) {
        float e = g_emis[((size_t)t * BB + b) * CC + j];
        float v[CC]; float m = -1e30f;
#pragma unroll
        for (int i = 0; i < CC; i++) {
            v[i] = __shfl_sync(0xffffffffu, alpha, i) + tr[i];
            m = fmaxf(m, v[i]);
        }
        float ssum = 0.f;
#pragma unroll
        for (int i = 0; i < CC; i++) ssum += expf(v[i] - m);
        float na = e + m + logf(ssum);
        bool mt = y[b * TT + t] > -1;
        alpha = mt ? na : alpha;
    }
    float val = (lane < CC) ? (alpha + crf_end[lane]) : -1e30f;
    float mm = val;
    for (int o = 16; o; o >>= 1) mm = fmaxf(mm, __shfl_xor_sync(0xffffffffu, mm, o));
    float se = expf(val - mm);
    for (int o = 16; o; o >>= 1) se += __shfl_xor_sync(0xffffffffu, se, o);
    float denom = mm + logf(se);
    if (lane == 0) g_llh[b] = score - denom;
}

// ---------------- 6) deterministic final reduction -------------------------------
__global__ void reduce_kernel(float* out) {
    __shared__ float sm[BB];
    int tid = threadIdx.x;
    sm[tid] = g_llh[tid];
    __syncthreads();
    for (int o = 64; o; o >>= 1) {
        if (tid < o) sm[tid] += sm[tid + o];
        __syncthreads();
    }
    if (tid == 0) out[0] = -sm[0] / (float)BB;
}

// ---------------- launch --------------------------------------------------------
extern "C" void kernel_launch(void* const* d_in, const int* in_sizes, int n_in,
                              void* d_out, int out_size) {
    (void)in_sizes; (void)n_in; (void)out_size;
    const int*   x         = (const int*)  d_in[0];
    const int*   y         = (const int*)  d_in[1];
    const float* embed     = (const float*)d_in[2];
    const float* w_ih_l0   = (const float*)d_in[3];
    const float* w_hh_l0   = (const float*)d_in[4];
    const float* b_l0      = (const float*)d_in[5];
    const float* w_ih_l1   = (const float*)d_in[6];
    const float* w_hh_l1   = (const float*)d_in[7];
    const float* b_l1      = (const float*)d_in[8];
    const float* cls_w     = (const float*)d_in[9];
    const float* cls_b     = (const float*)d_in[10];
    const float* crf_start = (const float*)d_in[11];
    const float* crf_end   = (const float*)d_in[12];
    const float* crf_trans = (const float*)d_in[13];
    float* out = (float*)d_out;

    const int SMEM_BYTES = (16384 + 32768) * 4 + 32 * ZPAD * 4;   // 213504
    static bool attr_set = false;
    if (!attr_set) {
        cudaFuncSetAttribute(recurrent_kernel<0>, cudaFuncAttributeMaxDynamicSharedMemorySize, SMEM_BYTES);
        cudaFuncSetAttribute(recurrent_kernel<1>, cudaFuncAttributeMaxDynamicSharedMemorySize, SMEM_BYTES);
        attr_set = true;
    }

    unsigned* xstf;  cudaGetSymbolAddress((void**)&xstf,  g_xstf);
    unsigned* hs0tf; cudaGetSymbolAddress((void**)&hs0tf, g_hs0tf);

    embed_kernel<<<TT * BB, 128>>>(x, embed);

    cvtw_kernel<<<(NN * HH / 4 + 255) / 256, 256>>>(w_ih_l0, HH);
    gemm_kernel<HH><<<dim3(32, 256), 256>>>(xstf, b_l0);
    recurrent_kernel<0><<<NCTA, 256, SMEM_BYTES>>>(w_hh_l0);

    cvtw_kernel<<<(NN * H2 / 4 + 255) / 256, 256>>>(w_ih_l1, H2);
    gemm_kernel<H2><<<dim3(32, 256), 256>>>(hs0tf, b_l1);
    recurrent_kernel<1><<<NCTA, 256, SMEM_BYTES>>>(w_hh_l1);

    emis_kernel<<<(TT * BB) / 8, 256>>>(cls_w, cls_b);
    crf_kernel<<<16, 256>>>(y, crf_start, crf_end, crf_trans);
    reduce_kernel<<<1, 128>>>(out);
}

// round 8
// speedup vs baseline: 9.9939x; 1.6539x over previous
#include <cuda_runtime.h>
#include <math.h>

// Problem constants
#define TT 256
#define BB 128
#define HH 512
#define H2 1024   // 2H
#define G4 2048   // 4H
#define NN 4096   // 2 dirs * 4H
#define CC 9
#define NCTA 128
#define NCTA_DIR 64
#define ZPAD 132

// ============ fp16 fragment-permuted global layouts (m16n8k16) =================
// A-perm (A operand, 16(m)x16(k) tiles), u32 packs 2 fp16 (even k = low half):
//   mt=m/16, kt=k/16, r=m%16, c=k%16
//   lane=(r&7)*4+((c>>1)&3), word=(r>>3)+2*(c>>3)
//   flat_u32 = ((mt*KT+kt)*32+lane)*4+word
// B-perm (B operand, 16(k)x8(n) tiles), u32 packs 2 fp16:
//   nt=n/8, kt=k/16, lane=(n&7)*4+((k>>1)&3), word=(k>>3)&1
//   flat_u32 = ((nt*KT+kt)*32+lane)*2+word

// ---------------- scratch (device globals) ----------------
__device__ unsigned g_xsh  [TT * BB * HH / 2];   // A-perm fp16 input (K=512)
__device__ float    g_pre  [TT * BB * NN];
__device__ unsigned g_hs0h [TT * BB * H2 / 2];   // A-perm fp16 layer-0 out (K=1024)
__device__ float    g_hs1  [TT * BB * H2];
__device__ float    g_c    [2 * BB * HH];
__device__ unsigned g_hh   [2][2 * 32768];       // B-perm fp16 h, [parity][dir*32768]
__device__ unsigned g_wh   [NN * H2 / 2];        // B-perm fp16 W_ih of current layer
__device__ float    g_emis [TT * BB * CC];
__device__ float    g_llh  [BB];
__device__ unsigned g_bar_count2[2] = {0, 0};
__device__ unsigned g_bar_phase2[2] = {0, 0};

// ---------------- helpers ----------------
__device__ __forceinline__ unsigned f2h2(float lo, float hi) {
    unsigned u;  // first src operand -> upper half, second -> lower half
    asm("cvt.rn.f16x2.f32 %0, %1, %2;" : "=r"(u) : "f"(hi), "f"(lo));
    return u;
}
__device__ __forceinline__ void mma_f16(float* c, unsigned a0, unsigned a1,
                                        unsigned a2, unsigned a3,
                                        unsigned b0, unsigned b1) {
    asm volatile("mma.sync.aligned.m16n8k16.row.col.f32.f16.f16.f32 "
                 "{%0,%1,%2,%3}, {%4,%5,%6,%7}, {%8,%9}, {%0,%1,%2,%3};"
                 : "+f"(c[0]), "+f"(c[1]), "+f"(c[2]), "+f"(c[3])
                 : "r"(a0), "r"(a1), "r"(a2), "r"(a3), "r"(b0), "r"(b1));
}
__device__ __forceinline__ void cp16(unsigned dst_smem, const void* src) {
    asm volatile("cp.async.ca.shared.global [%0], [%1], 16;" :: "r"(dst_smem), "l"(src));
}
#define CP_COMMIT() asm volatile("cp.async.commit_group;")
#define CP_WAIT(n)  asm volatile("cp.async.wait_group %0;" :: "n"(n))

// ---------------- 1) embedding gather + renorm -> A-perm fp16 --------------------
__global__ void embed_kernel(const int* __restrict__ x, const float* __restrict__ embed) {
    int row = blockIdx.x;           // m = t*B + b
    int t = row / BB, b = row % BB;
    int tok = x[b * TT + t];
    const float* e = embed + (size_t)tok * HH;
    int tid = threadIdx.x;          // 128 threads, thread owns k = tid*4 .. +3
    float4 v = *(const float4*)(e + tid * 4);
    float ss = v.x * v.x + v.y * v.y + v.z * v.z + v.w * v.w;
    for (int o = 16; o; o >>= 1) ss += __shfl_xor_sync(0xffffffffu, ss, o);
    __shared__ float red[4];
    if ((tid & 31) == 0) red[tid >> 5] = ss;
    __syncthreads();
    float total = red[0] + red[1] + red[2] + red[3];
    float nrm = sqrtf(total);
    float sc = (nrm > 1.0f) ? 1.0f / (nrm + 1e-7f) : 1.0f;
    int mt = row >> 4, r = row & 15;
    int k0 = tid * 4;
    int kt = k0 >> 4, c = k0 & 15;
    unsigned lane = (unsigned)((r & 7) * 4 + ((c >> 1) & 3));
    unsigned word = (unsigned)((r >> 3) + 2 * (c >> 3));
    size_t base = (((size_t)mt * 32 + kt) * 32 + lane) * 4 + word;
    g_xsh[base]     = f2h2(v.x * sc, v.y * sc);
    g_xsh[base + 4] = f2h2(v.z * sc, v.w * sc);   // lane+1, same word
}

// ---------------- W_ih -> B-perm fp16 --------------------------------------------
__global__ void cvtw_kernel(const float* __restrict__ W, int K) {
    int kq = K >> 2;
    int i = blockIdx.x * 256 + threadIdx.x;       // over NN*(K/4)
    if (i >= NN * kq) return;
    int n = i / kq, q = i - n * kq;
    float4 v = *(const float4*)(W + (size_t)n * K + q * 4);
    int k0 = q * 4;
    int kt = k0 >> 4;
    unsigned lane = (unsigned)((n & 7) * 4 + ((k0 >> 1) & 3));
    unsigned word = (unsigned)((k0 >> 3) & 1);
    size_t base = (((size_t)(n >> 3) * (K >> 4) + kt) * 32 + lane) * 2 + word;
    g_wh[base]     = f2h2(v.x, v.y);
    g_wh[base + 2] = f2h2(v.z, v.w);              // lane+1
}

// ---------------- 2) input projection GEMM (fp16 m16n8k16, 3-stage cp.async) -----
// C(32768 x 4096) = A @ W^T + bias. CTA tile 128x128 (8 m-tiles x 16 n-tiles),
// slab = 32 k (2 k16-tiles), 3-stage pipeline.
template <int K>
__global__ void __launch_bounds__(256) gemm_kernel(const unsigned* __restrict__ A,
                                                   const float* __restrict__ bias) {
    __shared__ unsigned a_s[3][2048];   // 8 mt x 2 kt x 128 u32
    __shared__ unsigned b_s[3][2048];   // 16 nt x 2 kt x 64 u32

    constexpr int KT = K >> 4;
    const int mt0 = blockIdx.y * 8, nt0 = blockIdx.x * 16;
    const int tid = threadIdx.x;
    const int w = tid >> 5, lane = tid & 31;
    const int wm = w >> 2, wn = w & 3;
    const int lr = lane >> 2, lc = lane & 3;

    unsigned a_base = (unsigned)__cvta_generic_to_shared(a_s);
    unsigned b_base = (unsigned)__cvta_generic_to_shared(b_s);

    float acc[4][4][4];
#pragma unroll
    for (int i = 0; i < 4; i++)
#pragma unroll
        for (int j = 0; j < 4; j++)
#pragma unroll
            for (int q = 0; q < 4; q++) acc[i][j][q] = 0.f;

    auto stage = [&](int sl, int st) {
        int kt0 = sl * 2;
#pragma unroll
        for (int rep = 0; rep < 2; rep++) {
            int c = tid + rep * 256;              // 0..511
            {   // A: 8 mt x 2 kt x 32 float4
                int mtl = c >> 6, ktl = (c >> 5) & 1, q = c & 31;
                const unsigned* src = A + (((size_t)(mt0 + mtl) * KT + kt0 + ktl) * 128 + q * 4);
                cp16(a_base + (st * 2048 + (mtl * 2 + ktl) * 128 + q * 4) * 4, src);
            }
            {   // B: 16 nt x 2 kt x 16 float4
                int ntl = c >> 5, ktl = (c >> 4) & 1, q = c & 15;
                const unsigned* src = g_wh + (((size_t)(nt0 + ntl) * KT + kt0 + ktl) * 64 + q * 4);
                cp16(b_base + (st * 2048 + (ntl * 2 + ktl) * 64 + q * 4) * 4, src);
            }
        }
    };

    constexpr int NS = KT / 2;
    stage(0, 0); CP_COMMIT();
    stage(1, 1); CP_COMMIT();
    int buf = 0;
    for (int it = 0; it < NS; it++) {
        if (it + 1 < NS) CP_WAIT(1); else CP_WAIT(0);
        __syncthreads();
        const unsigned* As = a_s[buf];
        const unsigned* Bs = b_s[buf];
#pragma unroll
        for (int ktl = 0; ktl < 2; ktl++) {
            uint4 af[4]; uint2 bf[4];
#pragma unroll
            for (int mf = 0; mf < 4; mf++)
                af[mf] = *(const uint4*)&As[((wm * 4 + mf) * 2 + ktl) * 128 + lane * 4];
#pragma unroll
            for (int nf = 0; nf < 4; nf++)
                bf[nf] = *(const uint2*)&Bs[((wn * 4 + nf) * 2 + ktl) * 64 + lane * 2];
#pragma unroll
            for (int mf = 0; mf < 4; mf++)
#pragma unroll
                for (int nf = 0; nf < 4; nf++)
                    mma_f16(acc[mf][nf], af[mf].x, af[mf].y, af[mf].z, af[mf].w,
                            bf[nf].x, bf[nf].y);
        }
        __syncthreads();
        if (it + 2 < NS) { stage(it + 2, (buf + 2) % 3); CP_COMMIT(); }
        buf = (buf + 1) % 3;
    }
    // epilogue
    const int m0 = mt0 * 16, n0 = nt0 * 8;
#pragma unroll
    for (int nf = 0; nf < 4; nf++) {
        int col = n0 + wn * 32 + nf * 8 + 2 * lc;
        float b0v = bias[col], b1v = bias[col + 1];
#pragma unroll
        for (int mf = 0; mf < 4; mf++) {
            int row = m0 + wm * 64 + mf * 16 + lr;
            *(float2*)&g_pre[(size_t)row * NN + col] =
                make_float2(acc[mf][nf][0] + b0v, acc[mf][nf][1] + b1v);
            *(float2*)&g_pre[(size_t)(row + 8) * NN + col] =
                make_float2(acc[mf][nf][2] + b0v, acc[mf][nf][3] + b1v);
        }
    }
}

// ---------------- 3) persistent recurrent kernel (fp16 m16n8k16) -----------------
// CTA ct: dir = ct>>6, j0 = (ct&63)*8 -> 32 z rows (2 m16-tiles) resident in SMEM
// (A-perm fp16, KT=32). h in g_hh (B-perm fp16 per dir), staged in 2 chunks... 4
// chunks of 8 k16-tiles (128 k each), double-buffered cp.async.
template <int L>
__global__ void __launch_bounds__(256, 1) recurrent_kernel(const float* __restrict__ w_hh) {
    extern __shared__ unsigned smu[];
    unsigned* wpack = smu;                    // [mt(2)][kt(32)][lane(32)][4] = 8192 u32
    unsigned* hpk   = smu + 8192;             // 2 bufs x [nt(16)][ktl(8)][lane(32)][2] = 2*8192
    float* z_sm = (float*)(smu + 8192 + 16384);   // [32][ZPAD]

    const int tid = threadIdx.x;
    const int ct  = blockIdx.x;
    const int dir = ct >> 6;
    const int j0  = (ct & 63) * 8;
    const int w = tid >> 5, lane = tid & 31;
    const int wh = w >> 2, wn = w & 3;
    const int lr = lane >> 2, lc = lane & 3;

    unsigned phase0 = *(volatile unsigned*)&g_bar_phase2[dir];
    unsigned hp_base = (unsigned)__cvta_generic_to_shared(hpk);

    // --- pack resident weights (A-perm fp16, rows r32 = g*8+jj) ---
#pragma unroll
    for (int i = 0; i < 16; i++) {
        int lin = tid + i * 256;             // 32 rows x 128 float4
        int r32 = lin >> 7, k4 = lin & 127;
        const float* wr = w_hh + ((size_t)dir * G4 + (size_t)(r32 >> 3) * HH + j0 + (r32 & 7)) * HH + k4 * 4;
        float4 wv = *(const float4*)wr;
        int mt = r32 >> 4, r = r32 & 15;
        int kt = k4 >> 2;
        unsigned lane0 = (unsigned)((r & 7) * 4 + 2 * (k4 & 1));
        unsigned word  = (unsigned)((r >> 3) + 2 * ((k4 >> 1) & 1));
        unsigned base = ((unsigned)(mt * 32 + kt) * 32 + lane0) * 4 + word;
        wpack[base]     = f2h2(wv.x, wv.y);
        wpack[base + 4] = f2h2(wv.z, wv.w);   // lane0+1
    }
    __syncthreads();

    const int pb  = tid >> 1;            // pointwise batch
    const int pjh = (tid & 1) * 4;       // pointwise j offset (0 or 4)

    for (int s = 0; s < TT; s++) {
        const int tidx = dir ? (TT - 1 - s) : s;

        // --- prefetch pointwise operands ---
        const float* p = g_pre + ((size_t)tidx * BB + pb) * NN + (size_t)dir * G4;
        float4 p0 = *(const float4*)(p + 0 * HH + j0 + pjh);
        float4 p1 = *(const float4*)(p + 1 * HH + j0 + pjh);
        float4 p2 = *(const float4*)(p + 2 * HH + j0 + pjh);
        float4 p3 = *(const float4*)(p + 3 * HH + j0 + pjh);
        float* cptr = g_c + ((size_t)dir * BB + pb) * HH + j0 + pjh;
        float4 cold = (s == 0) ? make_float4(0.f, 0.f, 0.f, 0.f) : *(float4*)cptr;

        float acc[4][4];
#pragma unroll
        for (int nf = 0; nf < 4; nf++)
#pragma unroll
            for (int q = 0; q < 4; q++) acc[nf][q] = 0.f;

        if (s > 0) {
            const unsigned* hsrc = g_hh[s & 1] + dir * 32768;
            // stage chunk kc (8 k16-tiles): contiguous per n-tile (512 u32)
            auto stageh = [&](int kc, int buf) {
#pragma unroll
                for (int i = 0; i < 8; i++) {
                    int c = tid + i * 256;            // 0..2047 uint4
                    int nt = c >> 7, off4 = c & 127;
                    cp16(hp_base + (unsigned)(buf * 8192 + nt * 512 + off4 * 4) * 4,
                         hsrc + ((size_t)nt * 32 + kc * 8) * 64 + off4 * 4);
                }
            };
            stageh(0, 0); CP_COMMIT();
#pragma unroll
            for (int kc = 0; kc < 4; kc++) {
                if (kc < 3) { stageh(kc + 1, (kc + 1) & 1); CP_COMMIT(); CP_WAIT(1); }
                else        { CP_WAIT(0); }
                __syncthreads();
                const unsigned* hp = hpk + (kc & 1) * 8192;
#pragma unroll
                for (int ls = 0; ls < 8; ls++) {
                    uint4 aa = *(const uint4*)&wpack[((wh * 32 + kc * 8 + ls) * 32 + lane) * 4];
#pragma unroll
                    for (int nf = 0; nf < 4; nf++) {
                        uint2 bb = *(const uint2*)&hp[((wn * 4 + nf) * 8 + ls) * 64 + lane * 2];
                        mma_f16(acc[nf], aa.x, aa.y, aa.z, aa.w, bb.x, bb.y);
                    }
                }
                __syncthreads();
            }
        }

        // --- z exchange ---
#pragma unroll
        for (int nf = 0; nf < 4; nf++) {
            int row = wh * 16 + lr;
            int col = wn * 32 + nf * 8 + 2 * lc;
            *(float2*)&z_sm[row * ZPAD + col]       = make_float2(acc[nf][0], acc[nf][1]);
            *(float2*)&z_sm[(row + 8) * ZPAD + col] = make_float2(acc[nf][2], acc[nf][3]);
        }
        __syncthreads();

        // --- fused LSTM pointwise ---
        {
            float pi[4] = {p0.x, p0.y, p0.z, p0.w};
            float pf[4] = {p1.x, p1.y, p1.z, p1.w};
            float pg[4] = {p2.x, p2.y, p2.z, p2.w};
            float po[4] = {p3.x, p3.y, p3.z, p3.w};
            float co[4] = {cold.x, cold.y, cold.z, cold.w};
            float hn[4], cn[4];
#pragma unroll
            for (int x = 0; x < 4; x++) {
                int jj = pjh + x;
                float zi = z_sm[(0 * 8 + jj) * ZPAD + pb] + pi[x];
                float zf = z_sm[(1 * 8 + jj) * ZPAD + pb] + pf[x];
                float zg = z_sm[(2 * 8 + jj) * ZPAD + pb] + pg[x];
                float zo = z_sm[(3 * 8 + jj) * ZPAD + pb] + po[x];
                float ig = 1.f / (1.f + expf(-zi));
                float fg = 1.f / (1.f + expf(-zf));
                float og = 1.f / (1.f + expf(-zo));
                cn[x] = fg * co[x] + ig * tanhf(zg);
                hn[x] = og * tanhf(cn[x]);
            }
            *(float4*)cptr = make_float4(cn[0], cn[1], cn[2], cn[3]);

            // publish h in B-perm fp16 for next step: (n=pb, k=j0+pjh+x), KT=32
            {
                int k0 = j0 + pjh;
                int kt = k0 >> 4;
                unsigned lane0 = (unsigned)((pb & 7) * 4 + ((k0 >> 1) & 3));
                unsigned word  = (unsigned)((k0 >> 3) & 1);
                unsigned* hd = g_hh[(s + 1) & 1] + dir * 32768;
                unsigned base = ((unsigned)((pb >> 3) * 32 + kt) * 32 + lane0) * 2 + word;
                hd[base]     = f2h2(hn[0], hn[1]);
                hd[base + 2] = f2h2(hn[2], hn[3]);
            }
            if (L == 0) {
                // publish hs0 in A-perm fp16 (K=1024, KT=64): m=tidx*128+pb, k=dir*512+j0+pjh
                int m = tidx * BB + pb;
                int mt = m >> 4, r = m & 15;
                int k = dir * HH + j0 + pjh;
                int kt = k >> 4, c = k & 15;
                unsigned lane0 = (unsigned)((r & 7) * 4 + ((c >> 1) & 3));
                unsigned word  = (unsigned)((r >> 3) + 2 * (c >> 3));
                size_t base = (((size_t)mt * 64 + kt) * 32 + lane0) * 4 + word;
                g_hs0h[base]     = f2h2(hn[0], hn[1]);
                g_hs0h[base + 4] = f2h2(hn[2], hn[3]);
            } else {
                *(float4*)(g_hs1 + ((size_t)tidx * BB + pb) * H2 + (size_t)dir * HH + j0 + pjh) =
                    make_float4(hn[0], hn[1], hn[2], hn[3]);
            }
        }

        // --- per-direction grid barrier ---
        if (s < TT - 1) {
            __threadfence();
            __syncthreads();
            if (tid == 0) {
                unsigned ticket = atomicAdd(&g_bar_count2[dir], 1u);
                if (ticket == NCTA_DIR - 1) {
                    g_bar_count2[dir] = 0;
                    __threadfence();
                    atomicAdd(&g_bar_phase2[dir], 1u);
                } else {
                    unsigned target = phase0 + (unsigned)(s + 1);
                    while ((int)(*(volatile unsigned*)&g_bar_phase2[dir] - target) < 0)
                        __nanosleep(32);
                }
                __threadfence();
            }
            __syncthreads();
        }
    }
}

// ---------------- 4) emissions (cls_w cached in SMEM) ----------------------------
__global__ void emis_kernel(const float* __restrict__ cls_w, const float* __restrict__ cls_b) {
    __shared__ float wsm[CC * H2];
    int tid = threadIdx.x;
    for (int i = tid; i < CC * H2; i += 256) wsm[i] = cls_w[i];
    __syncthreads();
    int warp = blockIdx.x * 8 + (tid >> 5);
    int lane = tid & 31;
    const float* h = g_hs1 + (size_t)warp * H2;
    float sum[CC];
#pragma unroll
    for (int c = 0; c < CC; c++) sum[c] = 0.f;
    for (int k = lane; k < H2; k += 32) {
        float hk = h[k];
#pragma unroll
        for (int c = 0; c < CC; c++) sum[c] += hk * wsm[c * H2 + k];
    }
#pragma unroll
    for (int c = 0; c < CC; c++) {
        float sc = sum[c];
        for (int o = 16; o; o >>= 1) sc += __shfl_xor_sync(0xffffffffu, sc, o);
        if (lane == 0) g_emis[(size_t)warp * CC + c] = sc + cls_b[c];
    }
}

// ---------------- 5) CRF score + forward algorithm, one warp per batch -----------
__global__ void crf_kernel(const int* __restrict__ y,
                           const float* __restrict__ crf_start,
                           const float* __restrict__ crf_end,
                           const float* __restrict__ crf_trans) {
    int b = (blockIdx.x * blockDim.x + threadIdx.x) >> 5;
    int lane = threadIdx.x & 31;
    if (b >= BB) return;

    float local = 0.f; int cnt = 0;
    for (int t = lane; t < TT; t += 32) {
        int yt = y[b * TT + t];
        int tag = yt > 0 ? yt : 0;
        float e = g_emis[((size_t)t * BB + b) * CC + tag];
        if (t == 0) {
            local += crf_start[tag] + e;
        } else {
            int yp = y[b * TT + t - 1];
            int tp = yp > 0 ? yp : 0;
            float m = (yt > -1) ? 1.f : 0.f;
            local += m * (crf_trans[tp * CC + tag] + e);
        }
        cnt += (yt > -1) ? 1 : 0;
    }
    for (int o = 16; o; o >>= 1) {
        local += __shfl_xor_sync(0xffffffffu, local, o);
        cnt   += __shfl_xor_sync(0xffffffffu, cnt, o);
    }
    int seq_end = cnt - 1;
    int ylast = y[b * TT + seq_end];
    float score = local + crf_end[ylast > 0 ? ylast : 0];

    int j = lane < CC ? lane : (CC - 1);
    float tr[CC];
#pragma unroll
    for (int i = 0; i < CC; i++) tr[i] = crf_trans[i * CC + j];
    float alpha = crf_start[j] + g_emis[(size_t)b * CC + j];
    for (int t = 1; t < TT; t++) {
        float e = g_emis[((size_t)t * BB + b) * CC + j];
        float v[CC]; float m = -1e30f;
#pragma unroll
        for (int i = 0; i < CC; i++) {
            v[i] = __shfl_sync(0xffffffffu, alpha, i) + tr[i];
            m = fmaxf(m, v[i]);
        }
        float ssum = 0.f;
#pragma unroll
        for (int i = 0; i < CC; i++) ssum += expf(v[i] - m);
        float na = e + m + logf(ssum);
        bool mt = y[b * TT + t] > -1;
        alpha = mt ? na : alpha;
    }
    float val = (lane < CC) ? (alpha + crf_end[lane]) : -1e30f;
    float mm = val;
    for (int o = 16; o; o >>= 1) mm = fmaxf(mm, __shfl_xor_sync(0xffffffffu, mm, o));
    float se = expf(val - mm);
    for (int o = 16; o; o >>= 1) se += __shfl_xor_sync(0xffffffffu, se, o);
    float denom = mm + logf(se);
    if (lane == 0) g_llh[b] = score - denom;
}

// ---------------- 6) deterministic final reduction -------------------------------
__global__ void reduce_kernel(float* out) {
    __shared__ float sm[BB];
    int tid = threadIdx.x;
    sm[tid] = g_llh[tid];
    __syncthreads();
    for (int o = 64; o; o >>= 1) {
        if (tid < o) sm[tid] += sm[tid + o];
        __syncthreads();
    }
    if (tid == 0) out[0] = -sm[0] / (float)BB;
}

// ---------------- launch --------------------------------------------------------
extern "C" void kernel_launch(void* const* d_in, const int* in_sizes, int n_in,
                              void* d_out, int out_size) {
    (void)in_sizes; (void)n_in; (void)out_size;
    const int*   x         = (const int*)  d_in[0];
    const int*   y         = (const int*)  d_in[1];
    const float* embed     = (const float*)d_in[2];
    const float* w_ih_l0   = (const float*)d_in[3];
    const float* w_hh_l0   = (const float*)d_in[4];
    const float* b_l0      = (const float*)d_in[5];
    const float* w_ih_l1   = (const float*)d_in[6];
    const float* w_hh_l1   = (const float*)d_in[7];
    const float* b_l1      = (const float*)d_in[8];
    const float* cls_w     = (const float*)d_in[9];
    const float* cls_b     = (const float*)d_in[10];
    const float* crf_start = (const float*)d_in[11];
    const float* crf_end   = (const float*)d_in[12];
    const float* crf_trans = (const float*)d_in[13];
    float* out = (float*)d_out;

    const int SMEM_BYTES = (8192 + 16384) * 4 + 32 * ZPAD * 4;   // 115200
    static bool attr_set = false;
    if (!attr_set) {
        cudaFuncSetAttribute(recurrent_kernel<0>, cudaFuncAttributeMaxDynamicSharedMemorySize, SMEM_BYTES);
        cudaFuncSetAttribute(recurrent_kernel<1>, cudaFuncAttributeMaxDynamicSharedMemorySize, SMEM_BYTES);
        attr_set = true;
    }

    unsigned* xsh;  cudaGetSymbolAddress((void**)&xsh,  g_xsh);
    unsigned* hs0h; cudaGetSymbolAddress((void**)&hs0h, g_hs0h);

    embed_kernel<<<TT * BB, 128>>>(x, embed);

    cvtw_kernel<<<(NN * HH / 4 + 255) / 256, 256>>>(w_ih_l0, HH);
    gemm_kernel<HH><<<dim3(32, 256), 256>>>(xsh, b_l0);
    recurrent_kernel<0><<<NCTA, 256, SMEM_BYTES>>>(w_hh_l0);

    cvtw_kernel<<<(NN * H2 / 4 + 255) / 256, 256>>>(w_ih_l1, H2);
    gemm_kernel<H2><<<dim3(32, 256), 256>>>(hs0h, b_l1);
    recurrent_kernel<1><<<NCTA, 256, SMEM_BYTES>>>(w_hh_l1);

    emis_kernel<<<(TT * BB) / 8, 256>>>(cls_w, cls_b);
    crf_kernel<<<16, 256>>>(y, crf_start, crf_end, crf_trans);
    reduce_kernel<<<1, 128>>>(out);
}

// round 9
// speedup vs baseline: 10.9851x; 1.0992x over previous
#include <cuda_runtime.h>
#include <math.h>

// Problem constants
#define TT 256
#define BB 128
#define HH 512
#define H2 1024   // 2H
#define G4 2048   // 4H
#define NN 4096   // 2 dirs * 4H
#define CC 9
#define NCTA 128
#define ZP 34     // z_sm row stride (even: float2-aligned)

// ============ fp16 fragment-permuted global layouts (m16n8k16) =================
// A-perm: mt=m/16, kt=k/16, r=m%16, c=k%16
//   lane=(r&7)*4+((c>>1)&3), word=(r>>3)+2*(c>>3); flat_u32=((mt*KT+kt)*32+lane)*4+word
// B-perm: nt=n/8, kt=k/16, lane=(n&7)*4+((k>>1)&3), word=(k>>3)&1
//   flat_u32=((nt*KT+kt)*32+lane)*2+word

// ---------------- scratch (device globals) ----------------
__device__ unsigned g_xsh  [TT * BB * HH / 2];   // A-perm fp16 input (K=512)
__device__ float    g_pre  [TT * BB * NN];
__device__ unsigned g_hs0h [TT * BB * H2 / 2];   // A-perm fp16 layer-0 out (K=1024)
__device__ float    g_hs1  [TT * BB * H2];
__device__ float    g_c    [2 * BB * HH];
__device__ unsigned g_hh   [2][2 * 32768];       // B-perm fp16 h, [parity][dir*32768]
__device__ unsigned g_wh   [NN * H2 / 2];        // B-perm fp16 W_ih of current layer
__device__ float    g_emis [TT * BB * CC];
__device__ float    g_llh  [BB];
__device__ unsigned g_bar_count8[8] = {0};       // per (dir, batch-group) barrier
__device__ unsigned g_bar_phase8[8] = {0};

// ---------------- helpers ----------------
__device__ __forceinline__ unsigned f2h2(float lo, float hi) {
    unsigned u;
    asm("cvt.rn.f16x2.f32 %0, %1, %2;" : "=r"(u) : "f"(hi), "f"(lo));
    return u;
}
__device__ __forceinline__ void mma_f16(float* c, unsigned a0, unsigned a1,
                                        unsigned a2, unsigned a3,
                                        unsigned b0, unsigned b1) {
    asm volatile("mma.sync.aligned.m16n8k16.row.col.f32.f16.f16.f32 "
                 "{%0,%1,%2,%3}, {%4,%5,%6,%7}, {%8,%9}, {%0,%1,%2,%3};"
                 : "+f"(c[0]), "+f"(c[1]), "+f"(c[2]), "+f"(c[3])
                 : "r"(a0), "r"(a1), "r"(a2), "r"(a3), "r"(b0), "r"(b1));
}
__device__ __forceinline__ void cp16(unsigned dst_smem, const void* src) {
    asm volatile("cp.async.ca.shared.global [%0], [%1], 16;" :: "r"(dst_smem), "l"(src));
}
#define CP_COMMIT() asm volatile("cp.async.commit_group;")
#define CP_WAIT(n)  asm volatile("cp.async.wait_group %0;" :: "n"(n))

// ---------------- 1) embedding gather + renorm -> A-perm fp16 --------------------
__global__ void embed_kernel(const int* __restrict__ x, const float* __restrict__ embed) {
    int row = blockIdx.x;           // m = t*B + b
    int t = row / BB, b = row % BB;
    int tok = x[b * TT + t];
    const float* e = embed + (size_t)tok * HH;
    int tid = threadIdx.x;
    float4 v = *(const float4*)(e + tid * 4);
    float ss = v.x * v.x + v.y * v.y + v.z * v.z + v.w * v.w;
    for (int o = 16; o; o >>= 1) ss += __shfl_xor_sync(0xffffffffu, ss, o);
    __shared__ float red[4];
    if ((tid & 31) == 0) red[tid >> 5] = ss;
    __syncthreads();
    float total = red[0] + red[1] + red[2] + red[3];
    float nrm = sqrtf(total);
    float sc = (nrm > 1.0f) ? 1.0f / (nrm + 1e-7f) : 1.0f;
    int mt = row >> 4, r = row & 15;
    int k0 = tid * 4;
    int kt = k0 >> 4, c = k0 & 15;
    unsigned lane = (unsigned)((r & 7) * 4 + ((c >> 1) & 3));
    unsigned word = (unsigned)((r >> 3) + 2 * (c >> 3));
    size_t base = (((size_t)mt * 32 + kt) * 32 + lane) * 4 + word;
    g_xsh[base]     = f2h2(v.x * sc, v.y * sc);
    g_xsh[base + 4] = f2h2(v.z * sc, v.w * sc);
}

// ---------------- W_ih -> B-perm fp16 --------------------------------------------
__global__ void cvtw_kernel(const float* __restrict__ W, int K) {
    int kq = K >> 2;
    int i = blockIdx.x * 256 + threadIdx.x;
    if (i >= NN * kq) return;
    int n = i / kq, q = i - n * kq;
    float4 v = *(const float4*)(W + (size_t)n * K + q * 4);
    int k0 = q * 4;
    int kt = k0 >> 4;
    unsigned lane = (unsigned)((n & 7) * 4 + ((k0 >> 1) & 3));
    unsigned word = (unsigned)((k0 >> 3) & 1);
    size_t base = (((size_t)(n >> 3) * (K >> 4) + kt) * 32 + lane) * 2 + word;
    g_wh[base]     = f2h2(v.x, v.y);
    g_wh[base + 2] = f2h2(v.z, v.w);
}

// ---------------- 2) input projection GEMM (fp16 m16n8k16, 3-stage cp.async) -----
template <int K>
__global__ void __launch_bounds__(256) gemm_kernel(const unsigned* __restrict__ A,
                                                   const float* __restrict__ bias) {
    __shared__ unsigned a_s[3][2048];
    __shared__ unsigned b_s[3][2048];

    constexpr int KT = K >> 4;
    const int mt0 = blockIdx.y * 8, nt0 = blockIdx.x * 16;
    const int tid = threadIdx.x;
    const int w = tid >> 5, lane = tid & 31;
    const int wm = w >> 2, wn = w & 3;
    const int lr = lane >> 2, lc = lane & 3;

    unsigned a_base = (unsigned)__cvta_generic_to_shared(a_s);
    unsigned b_base = (unsigned)__cvta_generic_to_shared(b_s);

    float acc[4][4][4];
#pragma unroll
    for (int i = 0; i < 4; i++)
#pragma unroll
        for (int j = 0; j < 4; j++)
#pragma unroll
            for (int q = 0; q < 4; q++) acc[i][j][q] = 0.f;

    auto stage = [&](int sl, int st) {
        int kt0 = sl * 2;
#pragma unroll
        for (int rep = 0; rep < 2; rep++) {
            int c = tid + rep * 256;
            {
                int mtl = c >> 6, ktl = (c >> 5) & 1, q = c & 31;
                const unsigned* src = A + (((size_t)(mt0 + mtl) * KT + kt0 + ktl) * 128 + q * 4);
                cp16(a_base + (st * 2048 + (mtl * 2 + ktl) * 128 + q * 4) * 4, src);
            }
            {
                int ntl = c >> 5, ktl = (c >> 4) & 1, q = c & 15;
                const unsigned* src = g_wh + (((size_t)(nt0 + ntl) * KT + kt0 + ktl) * 64 + q * 4);
                cp16(b_base + (st * 2048 + (ntl * 2 + ktl) * 64 + q * 4) * 4, src);
            }
        }
    };

    constexpr int NS = KT / 2;
    stage(0, 0); CP_COMMIT();
    stage(1, 1); CP_COMMIT();
    int buf = 0;
    for (int it = 0; it < NS; it++) {
        if (it + 1 < NS) CP_WAIT(1); else CP_WAIT(0);
        __syncthreads();
        const unsigned* As = a_s[buf];
        const unsigned* Bs = b_s[buf];
#pragma unroll
        for (int ktl = 0; ktl < 2; ktl++) {
            uint4 af[4]; uint2 bf[4];
#pragma unroll
            for (int mf = 0; mf < 4; mf++)
                af[mf] = *(const uint4*)&As[((wm * 4 + mf) * 2 + ktl) * 128 + lane * 4];
#pragma unroll
            for (int nf = 0; nf < 4; nf++)
                bf[nf] = *(const uint2*)&Bs[((wn * 4 + nf) * 2 + ktl) * 64 + lane * 2];
#pragma unroll
            for (int mf = 0; mf < 4; mf++)
#pragma unroll
                for (int nf = 0; nf < 4; nf++)
                    mma_f16(acc[mf][nf], af[mf].x, af[mf].y, af[mf].z, af[mf].w,
                            bf[nf].x, bf[nf].y);
        }
        __syncthreads();
        if (it + 2 < NS) { stage(it + 2, (buf + 2) % 3); CP_COMMIT(); }
        buf = (buf + 1) % 3;
    }
    const int m0 = mt0 * 16, n0 = nt0 * 8;
#pragma unroll
    for (int nf = 0; nf < 4; nf++) {
        int col = n0 + wn * 32 + nf * 8 + 2 * lc;
        float b0v = bias[col], b1v = bias[col + 1];
#pragma unroll
        for (int mf = 0; mf < 4; mf++) {
            int row = m0 + wm * 64 + mf * 16 + lr;
            *(float2*)&g_pre[(size_t)row * NN + col] =
                make_float2(acc[mf][nf][0] + b0v, acc[mf][nf][1] + b1v);
            *(float2*)&g_pre[(size_t)(row + 8) * NN + col] =
                make_float2(acc[mf][nf][2] + b0v, acc[mf][nf][3] + b1v);
        }
    }
}

// ---------------- 3) persistent recurrent kernel — 2D (j x batch) partition ------
// 128 CTAs: dir = ct>>6, bg = (ct&63)>>4 (32 batches), jg = ct&15 (32 j's).
// CTA holds 128 weight rows (4 gates x 32 j) resident in SMEM = 128KB fp16.
// Per step: stage 32KB h slice (4 n-tiles), z(128x32) = W @ h^T, fused gates.
// Barrier per (dir,bg): degree 16 (only CTAs sharing a batch group exchange h).
template <int L>
__global__ void __launch_bounds__(256, 1) recurrent_kernel(const float* __restrict__ w_hh) {
    extern __shared__ unsigned smu[];
    unsigned* wpack = smu;                    // [mt(8)][kt(32)][lane(32)][4] = 32768 u32
    unsigned* hpk   = smu + 32768;            // 2 bufs x [nt(4)][ktl(16)][lane(32)][2] = 2*4096
    float* z_sm = (float*)(smu + 32768 + 8192);   // [128][ZP]

    const int tid = threadIdx.x;
    const int ct  = blockIdx.x;
    const int dir = ct >> 6;
    const int ctl = ct & 63;
    const int bg  = ctl >> 4;                 // batch group (32 batches)
    const int jg  = ctl & 15;                 // j group (32 j)
    const int w = tid >> 5, lane = tid & 31;
    const int lr = lane >> 2, lc = lane & 3;
    const int baridx = dir * 4 + bg;

    unsigned phase0 = *(volatile unsigned*)&g_bar_phase8[baridx];
    unsigned hp_base = (unsigned)__cvta_generic_to_shared(hpk);

    // --- pack resident weights: local row r128 = g*32 + jj  (A-perm fp16, KT=32) ---
#pragma unroll
    for (int i = 0; i < 64; i++) {
        int lin = tid + i * 256;             // 128 rows x 128 float4
        int r128 = lin >> 7, k4 = lin & 127;
        int g = r128 >> 5, jj = r128 & 31;
        const float* wr = w_hh + ((size_t)dir * G4 + (size_t)g * HH + jg * 32 + jj) * HH + k4 * 4;
        float4 wv = *(const float4*)wr;
        int mt = r128 >> 4, r = r128 & 15;
        int kt = k4 >> 2;
        unsigned lane0 = (unsigned)((r & 7) * 4 + 2 * (k4 & 1));
        unsigned word  = (unsigned)((r >> 3) + 2 * ((k4 >> 1) & 1));
        unsigned base = ((unsigned)(mt * 32 + kt) * 32 + lane0) * 4 + word;
        wpack[base]     = f2h2(wv.x, wv.y);
        wpack[base + 4] = f2h2(wv.z, wv.w);
    }
    __syncthreads();

    const int bl = tid >> 3;             // pointwise local batch 0..31
    const int jq = tid & 7;              // pointwise j quad -> j_loc = jq*4..+3
    const int bgl = bg * 32 + bl;        // global batch
    const int jglob = jg * 32 + jq * 4;  // dir-relative j

    for (int s = 0; s < TT; s++) {
        const int tidx = dir ? (TT - 1 - s) : s;

        // --- prefetch pointwise operands (independent of h) ---
        const float* p = g_pre + ((size_t)tidx * BB + bgl) * NN + (size_t)dir * G4;
        float4 p0 = *(const float4*)(p + 0 * HH + jglob);
        float4 p1 = *(const float4*)(p + 1 * HH + jglob);
        float4 p2 = *(const float4*)(p + 2 * HH + jglob);
        float4 p3 = *(const float4*)(p + 3 * HH + jglob);
        float* cptr = g_c + ((size_t)dir * BB + bgl) * HH + jglob;
        float4 cold = (s == 0) ? make_float4(0.f, 0.f, 0.f, 0.f) : *(float4*)cptr;

        float acc[4][4];
#pragma unroll
        for (int nf = 0; nf < 4; nf++)
#pragma unroll
            for (int q = 0; q < 4; q++) acc[nf][q] = 0.f;

        if (s > 0) {
            const unsigned* hsrc = g_hh[s & 1] + dir * 32768;
            // stage chunk kc (16 k-tiles of this CTA's 4 n-tiles): 1024 uint4
            auto stageh = [&](int kc, int buf) {
#pragma unroll
                for (int i = 0; i < 4; i++) {
                    int c = tid + i * 256;            // 0..1023 uint4
                    int nt = c >> 8, off4 = c & 255;
                    cp16(hp_base + (unsigned)(buf * 4096 + nt * 1024 + off4 * 4) * 4,
                         hsrc + ((size_t)(bg * 4 + nt) * 32) * 64 + kc * 1024 + off4 * 4);
                }
            };
            stageh(0, 0); CP_COMMIT();
#pragma unroll
            for (int kc = 0; kc < 2; kc++) {
                if (kc == 0) { stageh(1, 1); CP_COMMIT(); CP_WAIT(1); }
                else         { CP_WAIT(0); }
                __syncthreads();
                const unsigned* hp = hpk + kc * 4096;
#pragma unroll
                for (int ls = 0; ls < 16; ls++) {
                    int kt = kc * 16 + ls;
                    uint4 aa = *(const uint4*)&wpack[((w * 32 + kt) * 32 + lane) * 4];
#pragma unroll
                    for (int nf = 0; nf < 4; nf++) {
                        uint2 bb = *(const uint2*)&hp[nf * 1024 + ls * 64 + lane * 2];
                        mma_f16(acc[nf], aa.x, aa.y, aa.z, aa.w, bb.x, bb.y);
                    }
                }
                __syncthreads();
            }
        }

        // --- z exchange: rows r128 = w*16 + lr (+8), cols nf*8 + 2lc (+1) ---
#pragma unroll
        for (int nf = 0; nf < 4; nf++) {
            int row = w * 16 + lr;
            int col = nf * 8 + 2 * lc;
            *(float2*)&z_sm[row * ZP + col]       = make_float2(acc[nf][0], acc[nf][1]);
            *(float2*)&z_sm[(row + 8) * ZP + col] = make_float2(acc[nf][2], acc[nf][3]);
        }
        __syncthreads();

        // --- fused LSTM pointwise: thread -> (batch bl, j_loc = jq*4..+3) ---
        {
            float pi[4] = {p0.x, p0.y, p0.z, p0.w};
            float pf[4] = {p1.x, p1.y, p1.z, p1.w};
            float pg[4] = {p2.x, p2.y, p2.z, p2.w};
            float po[4] = {p3.x, p3.y, p3.z, p3.w};
            float co[4] = {cold.x, cold.y, cold.z, cold.w};
            float hn[4], cn[4];
#pragma unroll
            for (int x = 0; x < 4; x++) {
                int jl = jq * 4 + x;
                float zi = z_sm[(0 * 32 + jl) * ZP + bl] + pi[x];
                float zf = z_sm[(1 * 32 + jl) * ZP + bl] + pf[x];
                float zg = z_sm[(2 * 32 + jl) * ZP + bl] + pg[x];
                float zo = z_sm[(3 * 32 + jl) * ZP + bl] + po[x];
                float ig = 1.f / (1.f + expf(-zi));
                float fg = 1.f / (1.f + expf(-zf));
                float og = 1.f / (1.f + expf(-zo));
                cn[x] = fg * co[x] + ig * tanhf(zg);
                hn[x] = og * tanhf(cn[x]);
            }
            *(float4*)cptr = make_float4(cn[0], cn[1], cn[2], cn[3]);

            // publish h in B-perm fp16 for next step: (n=bgl, k=jglob), KT=32
            {
                int kt = jglob >> 4, c = jglob & 15;
                unsigned lane0 = (unsigned)((bgl & 7) * 4 + ((c >> 1) & 3));
                unsigned word  = (unsigned)((c >> 3) & 1);
                unsigned* hd = g_hh[(s + 1) & 1] + dir * 32768;
                unsigned base = ((unsigned)((bgl >> 3) * 32 + kt) * 32 + lane0) * 2 + word;
                hd[base]     = f2h2(hn[0], hn[1]);
                hd[base + 2] = f2h2(hn[2], hn[3]);
            }
            if (L == 0) {
                // publish hs0 in A-perm fp16 (K=1024, KT=64): m=tidx*128+bgl, k=dir*512+jglob
                int m = tidx * BB + bgl;
                int mt = m >> 4, r = m & 15;
                int k = dir * HH + jglob;
                int kt = k >> 4, c = k & 15;
                unsigned lane0 = (unsigned)((r & 7) * 4 + ((c >> 1) & 3));
                unsigned word  = (unsigned)((r >> 3) + 2 * (c >> 3));
                size_t base = (((size_t)mt * 64 + kt) * 32 + lane0) * 4 + word;
                g_hs0h[base]     = f2h2(hn[0], hn[1]);
                g_hs0h[base + 4] = f2h2(hn[2], hn[3]);
            } else {
                *(float4*)(g_hs1 + ((size_t)tidx * BB + bgl) * H2 + (size_t)dir * HH + jglob) =
                    make_float4(hn[0], hn[1], hn[2], hn[3]);
            }
        }

        // --- per-(dir,bg) grid barrier, degree 16 ---
        if (s < TT - 1) {
            __threadfence();
            __syncthreads();
            if (tid == 0) {
                unsigned ticket = atomicAdd(&g_bar_count8[baridx], 1u);
                if (ticket == 15) {
                    g_bar_count8[baridx] = 0;
                    __threadfence();
                    atomicAdd(&g_bar_phase8[baridx], 1u);
                } else {
                    unsigned target = phase0 + (unsigned)(s + 1);
                    while ((int)(*(volatile unsigned*)&g_bar_phase8[baridx] - target) < 0)
                        __nanosleep(32);
                }
                __threadfence();
            }
            __syncthreads();
        }
    }
}

// ---------------- 4) emissions (cls_w cached in SMEM) ----------------------------
__global__ void emis_kernel(const float* __restrict__ cls_w, const float* __restrict__ cls_b) {
    __shared__ float wsm[CC * H2];
    int tid = threadIdx.x;
    for (int i = tid; i < CC * H2; i += 256) wsm[i] = cls_w[i];
    __syncthreads();
    int warp = blockIdx.x * 8 + (tid >> 5);
    int lane = tid & 31;
    const float* h = g_hs1 + (size_t)warp * H2;
    float sum[CC];
#pragma unroll
    for (int c = 0; c < CC; c++) sum[c] = 0.f;
    for (int k = lane; k < H2; k += 32) {
        float hk = h[k];
#pragma unroll
        for (int c = 0; c < CC; c++) sum[c] += hk * wsm[c * H2 + k];
    }
#pragma unroll
    for (int c = 0; c < CC; c++) {
        float sc = sum[c];
        for (int o = 16; o; o >>= 1) sc += __shfl_xor_sync(0xffffffffu, sc, o);
        if (lane == 0) g_emis[(size_t)warp * CC + c] = sc + cls_b[c];
    }
}

// ---------------- 5) CRF score + forward algorithm, one warp per batch -----------
__global__ void crf_kernel(const int* __restrict__ y,
                           const float* __restrict__ crf_start,
                           const float* __restrict__ crf_end,
                           const float* __restrict__ crf_trans) {
    int b = (blockIdx.x * blockDim.x + threadIdx.x) >> 5;
    int lane = threadIdx.x & 31;
    if (b >= BB) return;

    float local = 0.f; int cnt = 0;
    for (int t = lane; t < TT; t += 32) {
        int yt = y[b * TT + t];
        int tag = yt > 0 ? yt : 0;
        float e = g_emis[((size_t)t * BB + b) * CC + tag];
        if (t == 0) {
            local += crf_start[tag] + e;
        } else {
            int yp = y[b * TT + t - 1];
            int tp = yp > 0 ? yp : 0;
            float m = (yt > -1) ? 1.f : 0.f;
            local += m * (crf_trans[tp * CC + tag] + e);
        }
        cnt += (yt > -1) ? 1 : 0;
    }
    for (int o = 16; o; o >>= 1) {
        local += __shfl_xor_sync(0xffffffffu, local, o);
        cnt   += __shfl_xor_sync(0xffffffffu, cnt, o);
    }
    int seq_end = cnt - 1;
    int ylast = y[b * TT + seq_end];
    float score = local + crf_end[ylast > 0 ? ylast : 0];

    int j = lane < CC ? lane : (CC - 1);
    float tr[CC];
#pragma unroll
    for (int i = 0; i < CC; i++) tr[i] = crf_trans[i * CC + j];
    float alpha = crf_start[j] + g_emis[(size_t)b * CC + j];
    for (int t = 1; t < TT; t++) {
        float e = g_emis[((size_t)t * BB + b) * CC + j];
        float v[CC]; float m = -1e30f;
#pragma unroll
        for (int i = 0; i < CC; i++) {
            v[i] = __shfl_sync(0xffffffffu, alpha, i) + tr[i];
            m = fmaxf(m, v[i]);
        }
        float ssum = 0.f;
#pragma unroll
        for (int i = 0; i < CC; i++) ssum += expf(v[i] - m);
        float na = e + m + logf(ssum);
        bool mt = y[b * TT + t] > -1;
        alpha = mt ? na : alpha;
    }
    float val = (lane < CC) ? (alpha + crf_end[lane]) : -1e30f;
    float mm = val;
    for (int o = 16; o; o >>= 1) mm = fmaxf(mm, __shfl_xor_sync(0xffffffffu, mm, o));
    float se = expf(val - mm);
    for (int o = 16; o; o >>= 1) se += __shfl_xor_sync(0xffffffffu, se, o);
    float denom = mm + logf(se);
    if (lane == 0) g_llh[b] = score - denom;
}

// ---------------- 6) deterministic final reduction -------------------------------
__global__ void reduce_kernel(float* out) {
    __shared__ float sm[BB];
    int tid = threadIdx.x;
    sm[tid] = g_llh[tid];
    __syncthreads();
    for (int o = 64; o; o >>= 1) {
        if (tid < o) sm[tid] += sm[tid + o];
        __syncthreads();
    }
    if (tid == 0) out[0] = -sm[0] / (float)BB;
}

// ---------------- launch --------------------------------------------------------
extern "C" void kernel_launch(void* const* d_in, const int* in_sizes, int n_in,
                              void* d_out, int out_size) {
    (void)in_sizes; (void)n_in; (void)out_size;
    const int*   x         = (const int*)  d_in[0];
    const int*   y         = (const int*)  d_in[1];
    const float* embed     = (const float*)d_in[2];
    const float* w_ih_l0   = (const float*)d_in[3];
    const float* w_hh_l0   = (const float*)d_in[4];
    const float* b_l0      = (const float*)d_in[5];
    const float* w_ih_l1   = (const float*)d_in[6];
    const float* w_hh_l1   = (const float*)d_in[7];
    const float* b_l1      = (const float*)d_in[8];
    const float* cls_w     = (const float*)d_in[9];
    const float* cls_b     = (const float*)d_in[10];
    const float* crf_start = (const float*)d_in[11];
    const float* crf_end   = (const float*)d_in[12];
    const float* crf_trans = (const float*)d_in[13];
    float* out = (float*)d_out;

    // wpack 32768 u32 + hpk 8192 u32 + z_sm 128*ZP floats
    const int SMEM_BYTES = (32768 + 8192) * 4 + 128 * ZP * 4;   // 181248
    static bool attr_set = false;
    if (!attr_set) {
        cudaFuncSetAttribute(recurrent_kernel<0>, cudaFuncAttributeMaxDynamicSharedMemorySize, SMEM_BYTES);
        cudaFuncSetAttribute(recurrent_kernel<1>, cudaFuncAttributeMaxDynamicSharedMemorySize, SMEM_BYTES);
        attr_set = true;
    }

    unsigned* xsh;  cudaGetSymbolAddress((void**)&xsh,  g_xsh);
    unsigned* hs0h; cudaGetSymbolAddress((void**)&hs0h, g_hs0h);

    embed_kernel<<<TT * BB, 128>>>(x, embed);

    cvtw_kernel<<<(NN * HH / 4 + 255) / 256, 256>>>(w_ih_l0, HH);
    gemm_kernel<HH><<<dim3(32, 256), 256>>>(xsh, b_l0);
    recurrent_kernel<0><<<NCTA, 256, SMEM_BYTES>>>(w_hh_l0);

    cvtw_kernel<<<(NN * H2 / 4 + 255) / 256, 256>>>(w_ih_l1, H2);
    gemm_kernel<H2><<<dim3(32, 256), 256>>>(hs0h, b_l1);
    recurrent_kernel<1><<<NCTA, 256, SMEM_BYTES>>>(w_hh_l1);

    emis_kernel<<<(TT * BB) / 8, 256>>>(cls_w, cls_b);
    crf_kernel<<<16, 256>>>(y, crf_start, crf_end, crf_trans);
    reduce_kernel<<<1, 128>>>(out);
}